// round 9
// baseline (speedup 1.0000x reference)
#include <cuda_runtime.h>
#include <cuda_bf16.h>
#include <math.h>
#include <stdint.h>

#define HW 4096         // 64*64 spatial positions at feature res
#define CF 256          // feature channels
#define CO 64           // value channels (unalign_fb)
#define ALPHA 100.0f
#define NV 208          // GEMM2 cols: 3*64 warped + 3 E + 13 pad (13 n16 tiles)

// ---------------- device scratch (allocation-free) ----------------
__device__ uint32_t g_Xhi[(size_t)HW * HW / 2]; // bf16x2 hi plane (q,q+1)
__device__ uint32_t g_Xlo[(size_t)HW * HW / 2]; // bf16x2 lo plane
__device__ __nv_bfloat16 g_faHi[HW * CF];
__device__ __nv_bfloat16 g_faLo[HW * CF];
__device__ __nv_bfloat16 g_fbHi[HW * CF];
__device__ __nv_bfloat16 g_fbLo[HW * CF];
__device__ __nv_bfloat16 g_Vthi[NV * HW];    // V^T [col][q]
__device__ __nv_bfloat16 g_Vtlo[NV * HW];
__device__ float g_Wpart[4 * HW * NV];       // GEMM2 k-split partials
__device__ float g_ufb[HW * CO];             // downsampled values, [q][c]
__device__ float g_meanA[CF];
__device__ float g_meanB[CF];
__device__ unsigned char g_maskA[3 * HW];
__device__ unsigned char g_codeB[HW];        // 3-bit code of mask_b per q
__device__ float g_U0[CO];                   // sum_q ufb[q][c]
__device__ float g_Bk[3 * CO];               // B_k[c] = sum_{q in mb_k} ufb[q][c]
__device__ float g_nbk[3];                   // |mb_k|
__device__ float g_aligned[HW * CO];         // [p][c]

// ---------------- helpers ----------------
__device__ __forceinline__ uint32_t smem_u32(const void* p) {
    uint32_t a;
    asm("{ .reg .u64 t; cvta.to.shared.u64 t, %1; cvt.u32.u64 %0, t; }" : "=r"(a) : "l"(p));
    return a;
}

#define LDSM_X4(r0, r1, r2, r3, addr) \
    asm volatile("ldmatrix.sync.aligned.m8n8.x4.shared.b16 {%0,%1,%2,%3}, [%4];" \
        : "=r"(r0), "=r"(r1), "=r"(r2), "=r"(r3) : "r"(addr))

__device__ __forceinline__ void mma_bf16(float* c, const uint32_t* a, uint32_t b0, uint32_t b1) {
    asm volatile(
        "mma.sync.aligned.m16n8k16.row.col.f32.bf16.bf16.f32 "
        "{%0,%1,%2,%3}, {%4,%5,%6,%7}, {%8,%9}, {%0,%1,%2,%3};"
        : "+f"(c[0]), "+f"(c[1]), "+f"(c[2]), "+f"(c[3])
        : "r"(a[0]), "r"(a[1]), "r"(a[2]), "r"(a[3]), "r"(b0), "r"(b1));
}

__device__ __forceinline__ void cp16(uint32_t saddr, const void* g) {
    asm volatile("cp.async.cg.shared.global [%0], [%1], 16;" :: "r"(saddr), "l"(g));
}
#define CP_COMMIT asm volatile("cp.async.commit_group;" ::: "memory")
#define CP_WAIT2  asm volatile("cp.async.wait_group 2;" ::: "memory")

// ---------------- 1) masks ----------------
__global__ void k_masks(const int* __restrict__ fap, const int* __restrict__ fbp) {
    int p = blockIdx.x * 256 + threadIdx.x;
    if (p >= HW) return;
    int y = (p >> 6) << 2, x = (p & 63) << 2;
    int off = y * 256 + x;
    unsigned code = 0;
#pragma unroll
    for (int k = 0; k < 3; k++) {
        g_maskA[k * HW + p] = (fap[(k + 1) * 65536 + off] != 0) ? 1 : 0;
        if (fbp[(k + 1) * 65536 + off] != 0) code |= (1u << k);
    }
    g_codeB[p] = (unsigned char)code;
}

// ---------------- 2) per-channel spatial means ----------------
__global__ void k_mean(const float* __restrict__ fa, const float* __restrict__ fb) {
    int cb = blockIdx.x;
    int ch = cb & 255;
    const float* src = (cb < 256) ? fa : fb;
    float s = 0.f;
    for (int i = threadIdx.x; i < HW; i += 256) s += src[ch * HW + i];
    __shared__ float red[256];
    red[threadIdx.x] = s;
    __syncthreads();
    for (int st = 128; st > 0; st >>= 1) {
        if (threadIdx.x < st) red[threadIdx.x] += red[threadIdx.x + st];
        __syncthreads();
    }
    if (threadIdx.x == 0) {
        float m = red[0] / (float)HW;
        if (cb < 256) g_meanA[ch] = m; else g_meanB[ch] = m;
    }
}

// ---------------- 3) center + normalize + split, smem-transposed (coalesced) ----------------
__global__ void __launch_bounds__(256) k_norm(const float* __restrict__ fa,
                                              const float* __restrict__ fb) {
    __shared__ float sm[256 * 33];     // [c][p], stride 33 words
    int t = threadIdx.x;
    int pb = blockIdx.x * 32;
    const float* src;  const float* mean;
    __nv_bfloat16 *dHi, *dLo;
    if (blockIdx.y == 0) { src = fa; mean = g_meanA; dHi = g_faHi; dLo = g_faLo; }
    else                 { src = fb; mean = g_meanB; dHi = g_fbHi; dLo = g_fbLo; }

#pragma unroll
    for (int i = 0; i < 32; i++) {
        int v = t + i * 256;
        int c = v >> 5, p = v & 31;
        sm[c * 33 + p] = src[c * HW + pb + p] - mean[c];
    }
    __syncthreads();

    int p = t >> 3, part = t & 7;      // 8 threads per p, each owns 32 c
    float nsq = 0.f;
#pragma unroll
    for (int j = 0; j < 32; j++) {
        int c = part * 32 + ((j + part * 4) & 31);
        float v = sm[c * 33 + p];
        nsq += v * v;
    }
    nsq += __shfl_xor_sync(0xFFFFFFFF, nsq, 1);
    nsq += __shfl_xor_sync(0xFFFFFFFF, nsq, 2);
    nsq += __shfl_xor_sync(0xFFFFFFFF, nsq, 4);
    float inv = rsqrtf(nsq);

    size_t base = ((size_t)(pb + p) * CF + part * 32);
    uint32_t* hdst = (uint32_t*)(dHi + base);
    uint32_t* ldst = (uint32_t*)(dLo + base);
#pragma unroll
    for (int j = 0; j < 16; j++) {
        int c = part * 32 + j * 2;
        float v0 = sm[(c + 0) * 33 + p] * inv;
        float v1 = sm[(c + 1) * 33 + p] * inv;
        __nv_bfloat16 h0 = __float2bfloat16(v0), h1 = __float2bfloat16(v1);
        __nv_bfloat162 hp; hp.x = h0; hp.y = h1;
        __nv_bfloat16 l0 = __float2bfloat16(v0 - __bfloat162float(h0));
        __nv_bfloat16 l1 = __float2bfloat16(v1 - __bfloat162float(h1));
        __nv_bfloat162 lp; lp.x = l0; lp.y = l1;
        hdst[j] = *(uint32_t*)&hp;
        ldst[j] = *(uint32_t*)&lp;
    }
}

// ---------------- 4) bilinear downsample 256->64 ----------------
__global__ void k_ufb(const float* __restrict__ ub) {
    int idx = blockIdx.x * 256 + threadIdx.x;
    if (idx >= HW * CO) return;
    int c = idx & 63, q = idx >> 6;
    int i = q >> 6, j = q & 63;
    const float sc = 255.0f / 63.0f;
    float ry = (float)i * sc, rx = (float)j * sc;
    int y0 = (int)ry, x0 = (int)rx;
    int y1 = min(y0 + 1, 255), x1 = min(x0 + 1, 255);
    float wy = ry - (float)y0, wx = rx - (float)x0;
    const float* b = ub + c * 65536;
    float v00 = b[y0 * 256 + x0], v01 = b[y0 * 256 + x1];
    float v10 = b[y1 * 256 + x0], v11 = b[y1 * 256 + x1];
    float r0 = v00 * (1.f - wy) + v10 * wy;
    float r1 = v01 * (1.f - wy) + v11 * wy;
    g_ufb[q * CO + c] = r0 * (1.f - wx) + r1 * wx;
}

// ---------------- 5) U0[c], Bk[k][c], nbk ----------------
__global__ void k_ub() {
    int c = blockIdx.x;
    __shared__ float s_acc[4];
    __shared__ int   s_n[3];
    if (threadIdx.x < 4) s_acc[threadIdx.x] = 0.f;
    if (threadIdx.x < 3) s_n[threadIdx.x] = 0;
    __syncthreads();
    float a0 = 0, b0 = 0, b1 = 0, b2 = 0;
    int n0 = 0, n1 = 0, n2 = 0;
    for (int q = threadIdx.x; q < HW; q += 256) {
        float u = g_ufb[q * CO + c];
        int code = g_codeB[q];
        a0 += u;
        if (code & 1) { b0 += u; n0++; }
        if (code & 2) { b1 += u; n1++; }
        if (code & 4) { b2 += u; n2++; }
    }
    atomicAdd(&s_acc[0], a0);
    atomicAdd(&s_acc[1], b0);
    atomicAdd(&s_acc[2], b1);
    atomicAdd(&s_acc[3], b2);
    if (c == 0) {
        atomicAdd(&s_n[0], n0); atomicAdd(&s_n[1], n1); atomicAdd(&s_n[2], n2);
    }
    __syncthreads();
    if (threadIdx.x == 0) g_U0[c] = s_acc[0];
    if (threadIdx.x < 3) {
        g_Bk[threadIdx.x * CO + c] = s_acc[1 + threadIdx.x];
        if (c == 0) g_nbk[threadIdx.x] = (float)s_n[threadIdx.x];
    }
}

// ---------------- 5b) build V^T planes ----------------
__global__ void k_V() {
    int idx = blockIdx.x * 256 + threadIdx.x;   // col*HW + q
    if (idx >= NV * HW) return;
    int col = idx >> 12, q = idx & 4095;
    float v = 0.f;
    int code = g_codeB[q];
    if (col < 192) {
        int k = col >> 6, c = col & 63;
        v = ((code >> k) & 1) ? g_ufb[q * CO + c] : 0.f;
    } else if (col < 195) {
        v = (float)((code >> (col - 192)) & 1);
    }
    __nv_bfloat16 h = __float2bfloat16(v);
    g_Vthi[idx] = h;
    g_Vtlo[idx] = __float2bfloat16(v - __bfloat162float(h));
}

// ---------------- 6) GEMM1: split-bf16, 128x128 tile, 4-stage k16, B ping-pong ----------------
#define G1_RS 48                       // smem row stride (bytes)
#define G1_PLANE (128 * G1_RS)         // 6144
#define G1_STAGE (4 * G1_PLANE)        // 24576: Ahi, Alo, Bhi, Blo
#define G1_SMEM  (4 * G1_STAGE)        // 98304

__device__ __forceinline__ void g1_prefetch(uint32_t sb, int s, int kc,
                                            int pb, int qb, int t) {
    int kof = kc * 16;
#pragma unroll
    for (int i = 0; i < 4; i++) {
        int v = t + i * 256;                     // 0..1023
        int plane = v >> 8, r = (v >> 1) & 127, seg = v & 1;
        uint32_t sa = sb + (uint32_t)(s * G1_STAGE + plane * G1_PLANE + r * G1_RS + seg * 16);
        const __nv_bfloat16* src = (plane == 0) ? g_faHi : (plane == 1) ? g_faLo
                                 : (plane == 2) ? g_fbHi : g_fbLo;
        int rowb = (plane < 2) ? pb : qb;
        cp16(sa, (const char*)src + ((size_t)(rowb + r) * CF + kof + seg * 8) * 2);
    }
}

__global__ void __launch_bounds__(256) k_gemm_mma() {
    extern __shared__ char smem[];
    uint32_t sb = smem_u32(smem);
    int t = threadIdx.x, w = t >> 5, l = t & 31;
    int qb = blockIdx.x << 7, pb = blockIdx.y << 7;
    int wm = w >> 1, wn = w & 1;

    float acc[2][8][4] = {};

    int rowA = wm * 32 + (l & 15);
    int rowB = wn * 64 + (l & 15);
    uint32_t colb = (uint32_t)((l >> 4) << 4);

    g1_prefetch(sb, 0, 0, pb, qb, t); CP_COMMIT;
    g1_prefetch(sb, 1, 1, pb, qb, t); CP_COMMIT;
    g1_prefetch(sb, 2, 2, pb, qb, t); CP_COMMIT;

    for (int kc = 0; kc < 16; kc++) {
        CP_WAIT2;
        __syncthreads();
        if (kc <= 12) g1_prefetch(sb, (kc + 3) & 3, kc + 3, pb, qb, t);
        CP_COMMIT;

        uint32_t baseA = sb + (uint32_t)((kc & 3) * G1_STAGE);
        uint32_t baseB = baseA + 2 * G1_PLANE;

        uint32_t ah[2][4], al[2][4];
#pragma unroll
        for (int mi = 0; mi < 2; mi++) {
            uint32_t ad = baseA + (uint32_t)((rowA + mi * 16) * G1_RS) + colb;
            LDSM_X4(ah[mi][0], ah[mi][1], ah[mi][2], ah[mi][3], ad);
            LDSM_X4(al[mi][0], al[mi][1], al[mi][2], al[mi][3], ad + G1_PLANE);
        }

        uint32_t bh[2][4], bl[2][4];
        {
            uint32_t bd = baseB + (uint32_t)(rowB * G1_RS) + colb;
            LDSM_X4(bh[0][0], bh[0][1], bh[0][2], bh[0][3], bd);
            LDSM_X4(bl[0][0], bl[0][1], bl[0][2], bl[0][3], bd + G1_PLANE);
        }
#pragma unroll
        for (int np = 0; np < 4; np++) {
            int cur = np & 1, nxt = cur ^ 1;
            if (np < 3) {   // prefetch next B fragment before current MMAs
                uint32_t bd = baseB + (uint32_t)((rowB + (np + 1) * 16) * G1_RS) + colb;
                LDSM_X4(bh[nxt][0], bh[nxt][1], bh[nxt][2], bh[nxt][3], bd);
                LDSM_X4(bl[nxt][0], bl[nxt][1], bl[nxt][2], bl[nxt][3], bd + G1_PLANE);
            }
            mma_bf16(acc[0][np * 2 + 0], ah[0], bh[cur][0], bh[cur][2]);
            mma_bf16(acc[0][np * 2 + 1], ah[0], bh[cur][1], bh[cur][3]);
            mma_bf16(acc[1][np * 2 + 0], ah[1], bh[cur][0], bh[cur][2]);
            mma_bf16(acc[1][np * 2 + 1], ah[1], bh[cur][1], bh[cur][3]);
            mma_bf16(acc[0][np * 2 + 0], ah[0], bl[cur][0], bl[cur][2]);
            mma_bf16(acc[0][np * 2 + 1], ah[0], bl[cur][1], bl[cur][3]);
            mma_bf16(acc[1][np * 2 + 0], ah[1], bl[cur][0], bl[cur][2]);
            mma_bf16(acc[1][np * 2 + 1], ah[1], bl[cur][1], bl[cur][3]);
            mma_bf16(acc[0][np * 2 + 0], al[0], bh[cur][0], bh[cur][2]);
            mma_bf16(acc[0][np * 2 + 1], al[0], bh[cur][1], bh[cur][3]);
            mma_bf16(acc[1][np * 2 + 0], al[1], bh[cur][0], bh[cur][2]);
            mma_bf16(acc[1][np * 2 + 1], al[1], bh[cur][1], bh[cur][3]);
        }
    }

    // ---- epilogue: exp + bf16 hi/lo plane stores ----
    int prl = wm * 32 + (l >> 2);
    int qcl = wn * 64 + (l & 3) * 2;
#pragma unroll
    for (int mi = 0; mi < 2; mi++) {
#pragma unroll
        for (int nj = 0; nj < 8; nj++) {
#pragma unroll
            for (int half = 0; half < 2; half++) {
                int rloc = prl + mi * 16 + half * 8;
                int qloc = qcl + nj * 8;
                float x0 = __expf(fminf(ALPHA * acc[mi][nj][half * 2 + 0], 80.f));
                float x1 = __expf(fminf(ALPHA * acc[mi][nj][half * 2 + 1], 80.f));
                __nv_bfloat16 h0 = __float2bfloat16(x0);
                __nv_bfloat16 h1 = __float2bfloat16(x1);
                __nv_bfloat16 lo0 = __float2bfloat16(x0 - __bfloat162float(h0));
                __nv_bfloat16 lo1 = __float2bfloat16(x1 - __bfloat162float(h1));
                __nv_bfloat162 hp; hp.x = h0; hp.y = h1;
                __nv_bfloat162 lp; lp.x = lo0; lp.y = lo1;
                size_t idx = ((size_t)(pb + rloc) * HW + qb + qloc) >> 1;
                g_Xhi[idx] = *(uint32_t*)&hp;
                g_Xlo[idx] = *(uint32_t*)&lp;
            }
        }
    }
}

// ---------------- 7) GEMM2: W = X @ V^T, 4-stage k16, B ping-pong ----------------
#define G2_RS 48
#define G2_APLANE (64 * G2_RS)                    // 3072
#define G2_BPLANE (NV * G2_RS)                    // 9984
#define G2_STAGE (2 * G2_APLANE + 2 * G2_BPLANE)  // 26112
#define G2_SMEM  (4 * G2_STAGE)                   // 104448
#define G2_SLOTS (256 + 2 * NV * 2)               // 1088

__device__ __forceinline__ void g2_prefetch(uint32_t sb, int s, int qof, int pb, int t) {
#pragma unroll
    for (int i = 0; i < 5; i++) {
        int v = t + i * 256;
        if (v >= G2_SLOTS) break;
        if (v < 256) {
            int plane = v >> 7, r = (v >> 1) & 63, seg = v & 1;
            uint32_t sa = sb + (uint32_t)(s * G2_STAGE + plane * G2_APLANE + r * G2_RS + seg * 16);
            const uint32_t* xp = plane ? g_Xlo : g_Xhi;
            cp16(sa, (const char*)xp + ((size_t)(pb + r) * HW + qof) * 2 + seg * 16);
        } else {
            int v2 = v - 256;
            int plane = (v2 >= NV * 2) ? 1 : 0;
            int r = (v2 - plane * NV * 2) >> 1, seg = v2 & 1;
            uint32_t sa = sb + (uint32_t)(s * G2_STAGE + 2 * G2_APLANE + plane * G2_BPLANE + r * G2_RS + seg * 16);
            const __nv_bfloat16* vp = plane ? g_Vtlo : g_Vthi;
            cp16(sa, (const char*)vp + ((size_t)r * HW + qof + seg * 8) * 2);
        }
    }
}

__global__ void __launch_bounds__(256, 2) k_gemm2() {
    extern __shared__ char smem[];
    uint32_t sb = smem_u32(smem);
    int t = threadIdx.x, w = t >> 5, l = t & 31;
    int pb = blockIdx.x << 6;
    int q0 = blockIdx.y << 10;
    int wm = w & 3, wn = w >> 2;     // SMSP-balanced; wn0: 7 tiles, wn1: 6 tiles
    int nt = wn ? 6 : 7;

    float acc[14][4] = {};

    uint32_t arow = (uint32_t)((wm * 16 + (l & 15)) * G2_RS);
    uint32_t colb = (uint32_t)((l >> 4) << 4);

    g2_prefetch(sb, 0, q0, pb, t); CP_COMMIT;
    g2_prefetch(sb, 1, q0 + 16, pb, t); CP_COMMIT;
    g2_prefetch(sb, 2, q0 + 32, pb, t); CP_COMMIT;

    for (int kc = 0; kc < 64; kc++) {
        CP_WAIT2;
        __syncthreads();
        if (kc <= 60) g2_prefetch(sb, (kc + 3) & 3, q0 + (kc + 3) * 16, pb, t);
        CP_COMMIT;

        uint32_t baseA = sb + (uint32_t)((kc & 3) * G2_STAGE);
        uint32_t baseB = baseA + 2 * G2_APLANE;

        uint32_t ah[4], al[4];
        uint32_t ad = baseA + arow + colb;
        LDSM_X4(ah[0], ah[1], ah[2], ah[3], ad);
        LDSM_X4(al[0], al[1], al[2], al[3], ad + G2_APLANE);

        uint32_t bh[2][4], bl[2][4];
        {
            uint32_t bd = baseB + (uint32_t)((wn * 112 + (l & 15)) * G2_RS) + colb;
            LDSM_X4(bh[0][0], bh[0][1], bh[0][2], bh[0][3], bd);
            LDSM_X4(bl[0][0], bl[0][1], bl[0][2], bl[0][3], bd + G2_BPLANE);
        }
#pragma unroll
        for (int np = 0; np < 7; np++) {
            if (np < nt) {
                int cur = np & 1, nxt = cur ^ 1;
                if (np + 1 < nt) {
                    uint32_t bd = baseB + (uint32_t)((wn * 112 + (np + 1) * 16 + (l & 15)) * G2_RS) + colb;
                    LDSM_X4(bh[nxt][0], bh[nxt][1], bh[nxt][2], bh[nxt][3], bd);
                    LDSM_X4(bl[nxt][0], bl[nxt][1], bl[nxt][2], bl[nxt][3], bd + G2_BPLANE);
                }
                mma_bf16(acc[np * 2 + 0], ah, bh[cur][0], bh[cur][2]);
                mma_bf16(acc[np * 2 + 1], ah, bh[cur][1], bh[cur][3]);
                mma_bf16(acc[np * 2 + 0], ah, bl[cur][0], bl[cur][2]);
                mma_bf16(acc[np * 2 + 1], ah, bl[cur][1], bl[cur][3]);
                mma_bf16(acc[np * 2 + 0], al, bh[cur][0], bh[cur][2]);
                mma_bf16(acc[np * 2 + 1], al, bh[cur][1], bh[cur][3]);
            }
        }
    }

    // epilogue: fp32 partials
    int r0 = pb + wm * 16 + (l >> 2);
    int cb2 = (l & 3) * 2;
    float* Wp = g_Wpart + (size_t)blockIdx.y * HW * NV;
#pragma unroll
    for (int np = 0; np < 7; np++) {
        if (np < nt) {
#pragma unroll
            for (int n8 = 0; n8 < 2; n8++) {
                int col = wn * 112 + np * 16 + n8 * 8 + cb2;
                float* a = acc[np * 2 + n8];
                *(float2*)&Wp[(size_t)r0 * NV + col]       = make_float2(a[0], a[1]);
                *(float2*)&Wp[(size_t)(r0 + 8) * NV + col] = make_float2(a[2], a[3]);
            }
        }
    }
}

// ---------------- 8) combine (reads k-split partials directly) ----------------
__global__ void k_combine() {
    int idx = blockIdx.x * 256 + threadIdx.x;   // p*64 + c
    if (idx >= HW * CO) return;
    int p = idx >> 6, c = idx & 63;
    float comb = 0.f, msum = 0.f;
#pragma unroll
    for (int k = 0; k < 3; k++) {
        if (g_maskA[k * HW + p]) {
            msum += 1.f;
            float E = 0.f, Wv = 0.f;
#pragma unroll
            for (int ks = 0; ks < 4; ks++) {
                const float* Wp = g_Wpart + (size_t)ks * HW * NV + (size_t)p * NV;
                E  += Wp[192 + k];
                Wv += Wp[k * 64 + c];
            }
            float denom = E + (4096.0f - g_nbk[k]);
            comb += (Wv + g_U0[c] - g_Bk[k * CO + c]) / denom;
        }
    }
    g_aligned[idx] = comb / fmaxf(msum, 1.0f);
}

// ---------------- 9) bilinear upsample 64 -> 256 ----------------
__global__ void k_up(float* __restrict__ out) {
    int idx = blockIdx.x * 256 + threadIdx.x;
    if (idx >= CO * 65536) return;
    int c = idx >> 16, Y = (idx >> 8) & 255, X = idx & 255;
    const float sc = 63.0f / 255.0f;
    float ry = (float)Y * sc, rx = (float)X * sc;
    int y0 = (int)ry, x0 = (int)rx;
    int y1 = min(y0 + 1, 63), x1 = min(x0 + 1, 63);
    float wy = ry - (float)y0, wx = rx - (float)x0;
    const float* A = g_aligned;
    float v00 = A[((y0 << 6) + x0) * CO + c];
    float v01 = A[((y0 << 6) + x1) * CO + c];
    float v10 = A[((y1 << 6) + x0) * CO + c];
    float v11 = A[((y1 << 6) + x1) * CO + c];
    float r0 = v00 * (1.f - wy) + v10 * wy;
    float r1 = v01 * (1.f - wy) + v11 * wy;
    out[idx] = r0 * (1.f - wx) + r1 * wx;
}

// ---------------- launch ----------------
extern "C" void kernel_launch(void* const* d_in, const int* in_sizes, int n_in,
                              void* d_out, int out_size) {
    const float* ufb_in = (const float*)d_in[0];   // (1,64,256,256)
    const float* fa     = (const float*)d_in[1];   // (1,256,64,64)
    const int*   fap    = (const int*)  d_in[2];   // (1,4,256,256)
    const float* fb     = (const float*)d_in[3];   // (1,256,64,64)
    const int*   fbp    = (const int*)  d_in[4];   // (1,4,256,256)
    float* out = (float*)d_out;                    // (1,64,256,256)

    cudaFuncSetAttribute(k_gemm_mma, cudaFuncAttributeMaxDynamicSharedMemorySize, G1_SMEM);
    cudaFuncSetAttribute(k_gemm2,    cudaFuncAttributeMaxDynamicSharedMemorySize, G2_SMEM);

    k_masks<<<16, 256>>>(fap, fbp);
    k_mean<<<512, 256>>>(fa, fb);
    k_norm<<<dim3(128, 2), 256>>>(fa, fb);
    k_gemm_mma<<<dim3(32, 32), 256, G1_SMEM>>>();          // 4th launch -> profiled
    k_ufb<<<(HW * CO) / 256, 256>>>(ufb_in);
    k_ub<<<64, 256>>>();
    k_V<<<(NV * HW) / 256, 256>>>();
    k_gemm2<<<dim3(64, 4), 256, G2_SMEM>>>();
    k_combine<<<(HW * CO) / 256, 256>>>();
    k_up<<<(CO * 65536) / 256, 256>>>(out);
}

// round 10
// speedup vs baseline: 1.0509x; 1.0509x over previous
#include <cuda_runtime.h>
#include <cuda_bf16.h>
#include <math.h>
#include <stdint.h>

#define HW 4096         // 64*64 spatial positions at feature res
#define CF 256          // feature channels
#define CO 64           // value channels (unalign_fb)
#define ALPHA 100.0f
#define NV 208          // GEMM2 cols: 3*64 warped + 3 E + 13 pad (13 n16 tiles)

// ---------------- device scratch (allocation-free) ----------------
__device__ uint32_t g_Xhi[(size_t)HW * HW / 2]; // bf16x2 hi plane (q,q+1)
__device__ uint32_t g_Xlo[(size_t)HW * HW / 2]; // bf16x2 lo plane
__device__ __nv_bfloat16 g_faHi[HW * CF];
__device__ __nv_bfloat16 g_faLo[HW * CF];
__device__ __nv_bfloat16 g_fbHi[HW * CF];
__device__ __nv_bfloat16 g_fbLo[HW * CF];
__device__ __nv_bfloat16 g_Vthi[NV * HW];    // V^T [col][q]
__device__ __nv_bfloat16 g_Vtlo[NV * HW];
__device__ float g_Wpart[4 * HW * NV];       // GEMM2 k-split partials
__device__ float g_ufb[HW * CO];             // downsampled values, [q][c]
__device__ float g_meanA[CF];
__device__ float g_meanB[CF];
__device__ unsigned char g_maskA[3 * HW];
__device__ unsigned char g_codeB[HW];        // 3-bit code of mask_b per q
__device__ float g_U0[CO];                   // sum_q ufb[q][c]
__device__ float g_Bk[3 * CO];               // B_k[c] = sum_{q in mb_k} ufb[q][c]
__device__ float g_nbk[3];                   // |mb_k|
__device__ float g_aligned[HW * CO];         // [p][c]

// ---------------- helpers ----------------
__device__ __forceinline__ uint32_t smem_u32(const void* p) {
    uint32_t a;
    asm("{ .reg .u64 t; cvta.to.shared.u64 t, %1; cvt.u32.u64 %0, t; }" : "=r"(a) : "l"(p));
    return a;
}

#define LDSM_X4(r0, r1, r2, r3, addr) \
    asm volatile("ldmatrix.sync.aligned.m8n8.x4.shared.b16 {%0,%1,%2,%3}, [%4];" \
        : "=r"(r0), "=r"(r1), "=r"(r2), "=r"(r3) : "r"(addr))

__device__ __forceinline__ void mma_bf16(float* c, const uint32_t* a, uint32_t b0, uint32_t b1) {
    asm volatile(
        "mma.sync.aligned.m16n8k16.row.col.f32.bf16.bf16.f32 "
        "{%0,%1,%2,%3}, {%4,%5,%6,%7}, {%8,%9}, {%0,%1,%2,%3};"
        : "+f"(c[0]), "+f"(c[1]), "+f"(c[2]), "+f"(c[3])
        : "r"(a[0]), "r"(a[1]), "r"(a[2]), "r"(a[3]), "r"(b0), "r"(b1));
}

__device__ __forceinline__ void cp16(uint32_t saddr, const void* g) {
    asm volatile("cp.async.cg.shared.global [%0], [%1], 16;" :: "r"(saddr), "l"(g));
}
#define CP_COMMIT asm volatile("cp.async.commit_group;" ::: "memory")
#define CP_WAIT2  asm volatile("cp.async.wait_group 2;" ::: "memory")

// ---------------- 1) masks ----------------
__global__ void k_masks(const int* __restrict__ fap, const int* __restrict__ fbp) {
    int p = blockIdx.x * 256 + threadIdx.x;
    if (p >= HW) return;
    int y = (p >> 6) << 2, x = (p & 63) << 2;
    int off = y * 256 + x;
    unsigned code = 0;
#pragma unroll
    for (int k = 0; k < 3; k++) {
        g_maskA[k * HW + p] = (fap[(k + 1) * 65536 + off] != 0) ? 1 : 0;
        if (fbp[(k + 1) * 65536 + off] != 0) code |= (1u << k);
    }
    g_codeB[p] = (unsigned char)code;
}

// ---------------- 2) per-channel spatial means ----------------
__global__ void k_mean(const float* __restrict__ fa, const float* __restrict__ fb) {
    int cb = blockIdx.x;
    int ch = cb & 255;
    const float* src = (cb < 256) ? fa : fb;
    float s = 0.f;
    for (int i = threadIdx.x; i < HW; i += 256) s += src[ch * HW + i];
    __shared__ float red[256];
    red[threadIdx.x] = s;
    __syncthreads();
    for (int st = 128; st > 0; st >>= 1) {
        if (threadIdx.x < st) red[threadIdx.x] += red[threadIdx.x + st];
        __syncthreads();
    }
    if (threadIdx.x == 0) {
        float m = red[0] / (float)HW;
        if (cb < 256) g_meanA[ch] = m; else g_meanB[ch] = m;
    }
}

// ---------------- 3) center + normalize + split, smem-transposed (coalesced) ----------------
__global__ void __launch_bounds__(256) k_norm(const float* __restrict__ fa,
                                              const float* __restrict__ fb) {
    __shared__ float sm[256 * 33];     // [c][p], stride 33 words
    int t = threadIdx.x;
    int pb = blockIdx.x * 32;
    const float* src;  const float* mean;
    __nv_bfloat16 *dHi, *dLo;
    if (blockIdx.y == 0) { src = fa; mean = g_meanA; dHi = g_faHi; dLo = g_faLo; }
    else                 { src = fb; mean = g_meanB; dHi = g_fbHi; dLo = g_fbLo; }

#pragma unroll
    for (int i = 0; i < 32; i++) {
        int v = t + i * 256;
        int c = v >> 5, p = v & 31;
        sm[c * 33 + p] = src[c * HW + pb + p] - mean[c];
    }
    __syncthreads();

    int p = t >> 3, part = t & 7;      // 8 threads per p, each owns 32 c
    float nsq = 0.f;
#pragma unroll
    for (int j = 0; j < 32; j++) {
        int c = part * 32 + ((j + part * 4) & 31);
        float v = sm[c * 33 + p];
        nsq += v * v;
    }
    nsq += __shfl_xor_sync(0xFFFFFFFF, nsq, 1);
    nsq += __shfl_xor_sync(0xFFFFFFFF, nsq, 2);
    nsq += __shfl_xor_sync(0xFFFFFFFF, nsq, 4);
    float inv = rsqrtf(nsq);

    size_t base = ((size_t)(pb + p) * CF + part * 32);
    uint32_t* hdst = (uint32_t*)(dHi + base);
    uint32_t* ldst = (uint32_t*)(dLo + base);
#pragma unroll
    for (int j = 0; j < 16; j++) {
        int c = part * 32 + j * 2;
        float v0 = sm[(c + 0) * 33 + p] * inv;
        float v1 = sm[(c + 1) * 33 + p] * inv;
        __nv_bfloat16 h0 = __float2bfloat16(v0), h1 = __float2bfloat16(v1);
        __nv_bfloat162 hp; hp.x = h0; hp.y = h1;
        __nv_bfloat16 l0 = __float2bfloat16(v0 - __bfloat162float(h0));
        __nv_bfloat16 l1 = __float2bfloat16(v1 - __bfloat162float(h1));
        __nv_bfloat162 lp; lp.x = l0; lp.y = l1;
        hdst[j] = *(uint32_t*)&hp;
        ldst[j] = *(uint32_t*)&lp;
    }
}

// ---------------- 4) bilinear downsample 256->64 ----------------
__global__ void k_ufb(const float* __restrict__ ub) {
    int idx = blockIdx.x * 256 + threadIdx.x;
    if (idx >= HW * CO) return;
    int c = idx & 63, q = idx >> 6;
    int i = q >> 6, j = q & 63;
    const float sc = 255.0f / 63.0f;
    float ry = (float)i * sc, rx = (float)j * sc;
    int y0 = (int)ry, x0 = (int)rx;
    int y1 = min(y0 + 1, 255), x1 = min(x0 + 1, 255);
    float wy = ry - (float)y0, wx = rx - (float)x0;
    const float* b = ub + c * 65536;
    float v00 = b[y0 * 256 + x0], v01 = b[y0 * 256 + x1];
    float v10 = b[y1 * 256 + x0], v11 = b[y1 * 256 + x1];
    float r0 = v00 * (1.f - wy) + v10 * wy;
    float r1 = v01 * (1.f - wy) + v11 * wy;
    g_ufb[q * CO + c] = r0 * (1.f - wx) + r1 * wx;
}

// ---------------- 5) U0[c], Bk[k][c], nbk ----------------
__global__ void k_ub() {
    int c = blockIdx.x;
    __shared__ float s_acc[4];
    __shared__ int   s_n[3];
    if (threadIdx.x < 4) s_acc[threadIdx.x] = 0.f;
    if (threadIdx.x < 3) s_n[threadIdx.x] = 0;
    __syncthreads();
    float a0 = 0, b0 = 0, b1 = 0, b2 = 0;
    int n0 = 0, n1 = 0, n2 = 0;
    for (int q = threadIdx.x; q < HW; q += 256) {
        float u = g_ufb[q * CO + c];
        int code = g_codeB[q];
        a0 += u;
        if (code & 1) { b0 += u; n0++; }
        if (code & 2) { b1 += u; n1++; }
        if (code & 4) { b2 += u; n2++; }
    }
    atomicAdd(&s_acc[0], a0);
    atomicAdd(&s_acc[1], b0);
    atomicAdd(&s_acc[2], b1);
    atomicAdd(&s_acc[3], b2);
    if (c == 0) {
        atomicAdd(&s_n[0], n0); atomicAdd(&s_n[1], n1); atomicAdd(&s_n[2], n2);
    }
    __syncthreads();
    if (threadIdx.x == 0) g_U0[c] = s_acc[0];
    if (threadIdx.x < 3) {
        g_Bk[threadIdx.x * CO + c] = s_acc[1 + threadIdx.x];
        if (c == 0) g_nbk[threadIdx.x] = (float)s_n[threadIdx.x];
    }
}

// ---------------- 5b) build V^T planes ----------------
__global__ void k_V() {
    int idx = blockIdx.x * 256 + threadIdx.x;   // col*HW + q
    if (idx >= NV * HW) return;
    int col = idx >> 12, q = idx & 4095;
    float v = 0.f;
    int code = g_codeB[q];
    if (col < 192) {
        int k = col >> 6, c = col & 63;
        v = ((code >> k) & 1) ? g_ufb[q * CO + c] : 0.f;
    } else if (col < 195) {
        v = (float)((code >> (col - 192)) & 1);
    }
    __nv_bfloat16 h = __float2bfloat16(v);
    g_Vthi[idx] = h;
    g_Vtlo[idx] = __float2bfloat16(v - __bfloat162float(h));
}

// ---------------- 6) GEMM1: split-bf16, 128x128 tile, 4-stage k16, B ping-pong ----------------
#define G1_RS 48                       // smem row stride (bytes)
#define G1_PLANE (128 * G1_RS)         // 6144
#define G1_STAGE (4 * G1_PLANE)        // 24576: Ahi, Alo, Bhi, Blo
#define G1_SMEM  (4 * G1_STAGE)        // 98304

__device__ __forceinline__ void g1_prefetch(uint32_t sb, int s, int kc,
                                            int pb, int qb, int t) {
    int kof = kc * 16;
#pragma unroll
    for (int i = 0; i < 4; i++) {
        int v = t + i * 256;                     // 0..1023
        int plane = v >> 8, r = (v >> 1) & 127, seg = v & 1;
        uint32_t sa = sb + (uint32_t)(s * G1_STAGE + plane * G1_PLANE + r * G1_RS + seg * 16);
        const __nv_bfloat16* src = (plane == 0) ? g_faHi : (plane == 1) ? g_faLo
                                 : (plane == 2) ? g_fbHi : g_fbLo;
        int rowb = (plane < 2) ? pb : qb;
        cp16(sa, (const char*)src + ((size_t)(rowb + r) * CF + kof + seg * 8) * 2);
    }
}

__global__ void __launch_bounds__(256) k_gemm_mma() {
    extern __shared__ char smem[];
    uint32_t sb = smem_u32(smem);
    int t = threadIdx.x, w = t >> 5, l = t & 31;
    int qb = blockIdx.x << 7, pb = blockIdx.y << 7;
    int wm = w >> 1, wn = w & 1;

    float acc[2][8][4] = {};

    int rowA = wm * 32 + (l & 15);
    int rowB = wn * 64 + (l & 15);
    uint32_t colb = (uint32_t)((l >> 4) << 4);

    g1_prefetch(sb, 0, 0, pb, qb, t); CP_COMMIT;
    g1_prefetch(sb, 1, 1, pb, qb, t); CP_COMMIT;
    g1_prefetch(sb, 2, 2, pb, qb, t); CP_COMMIT;

    for (int kc = 0; kc < 16; kc++) {
        CP_WAIT2;
        __syncthreads();
        if (kc <= 12) g1_prefetch(sb, (kc + 3) & 3, kc + 3, pb, qb, t);
        CP_COMMIT;

        uint32_t baseA = sb + (uint32_t)((kc & 3) * G1_STAGE);
        uint32_t baseB = baseA + 2 * G1_PLANE;

        uint32_t ah[2][4], al[2][4];
#pragma unroll
        for (int mi = 0; mi < 2; mi++) {
            uint32_t ad = baseA + (uint32_t)((rowA + mi * 16) * G1_RS) + colb;
            LDSM_X4(ah[mi][0], ah[mi][1], ah[mi][2], ah[mi][3], ad);
            LDSM_X4(al[mi][0], al[mi][1], al[mi][2], al[mi][3], ad + G1_PLANE);
        }

        uint32_t bh[2][4], bl[2][4];
        {
            uint32_t bd = baseB + (uint32_t)(rowB * G1_RS) + colb;
            LDSM_X4(bh[0][0], bh[0][1], bh[0][2], bh[0][3], bd);
            LDSM_X4(bl[0][0], bl[0][1], bl[0][2], bl[0][3], bd + G1_PLANE);
        }
#pragma unroll
        for (int np = 0; np < 4; np++) {
            int cur = np & 1, nxt = cur ^ 1;
            if (np < 3) {
                uint32_t bd = baseB + (uint32_t)((rowB + (np + 1) * 16) * G1_RS) + colb;
                LDSM_X4(bh[nxt][0], bh[nxt][1], bh[nxt][2], bh[nxt][3], bd);
                LDSM_X4(bl[nxt][0], bl[nxt][1], bl[nxt][2], bl[nxt][3], bd + G1_PLANE);
            }
            mma_bf16(acc[0][np * 2 + 0], ah[0], bh[cur][0], bh[cur][2]);
            mma_bf16(acc[0][np * 2 + 1], ah[0], bh[cur][1], bh[cur][3]);
            mma_bf16(acc[1][np * 2 + 0], ah[1], bh[cur][0], bh[cur][2]);
            mma_bf16(acc[1][np * 2 + 1], ah[1], bh[cur][1], bh[cur][3]);
            mma_bf16(acc[0][np * 2 + 0], ah[0], bl[cur][0], bl[cur][2]);
            mma_bf16(acc[0][np * 2 + 1], ah[0], bl[cur][1], bl[cur][3]);
            mma_bf16(acc[1][np * 2 + 0], ah[1], bl[cur][0], bl[cur][2]);
            mma_bf16(acc[1][np * 2 + 1], ah[1], bl[cur][1], bl[cur][3]);
            mma_bf16(acc[0][np * 2 + 0], al[0], bh[cur][0], bh[cur][2]);
            mma_bf16(acc[0][np * 2 + 1], al[0], bh[cur][1], bh[cur][3]);
            mma_bf16(acc[1][np * 2 + 0], al[1], bh[cur][0], bh[cur][2]);
            mma_bf16(acc[1][np * 2 + 1], al[1], bh[cur][1], bh[cur][3]);
        }
    }

    // ---- epilogue: exp + bf16 hi/lo plane stores ----
    int prl = wm * 32 + (l >> 2);
    int qcl = wn * 64 + (l & 3) * 2;
#pragma unroll
    for (int mi = 0; mi < 2; mi++) {
#pragma unroll
        for (int nj = 0; nj < 8; nj++) {
#pragma unroll
            for (int half = 0; half < 2; half++) {
                int rloc = prl + mi * 16 + half * 8;
                int qloc = qcl + nj * 8;
                float x0 = __expf(fminf(ALPHA * acc[mi][nj][half * 2 + 0], 80.f));
                float x1 = __expf(fminf(ALPHA * acc[mi][nj][half * 2 + 1], 80.f));
                __nv_bfloat16 h0 = __float2bfloat16(x0);
                __nv_bfloat16 h1 = __float2bfloat16(x1);
                __nv_bfloat16 lo0 = __float2bfloat16(x0 - __bfloat162float(h0));
                __nv_bfloat16 lo1 = __float2bfloat16(x1 - __bfloat162float(h1));
                __nv_bfloat162 hp; hp.x = h0; hp.y = h1;
                __nv_bfloat162 lp; lp.x = lo0; lp.y = lo1;
                size_t idx = ((size_t)(pb + rloc) * HW + qb + qloc) >> 1;
                g_Xhi[idx] = *(uint32_t*)&hp;
                g_Xlo[idx] = *(uint32_t*)&lp;
            }
        }
    }
}

// ---------------- 7) GEMM2: W = X @ V^T, 4-stage k16, B ping-pong ----------------
#define G2_RS 48
#define G2_APLANE (64 * G2_RS)                    // 3072
#define G2_BPLANE (NV * G2_RS)                    // 9984
#define G2_STAGE (2 * G2_APLANE + 2 * G2_BPLANE)  // 26112
#define G2_SMEM  (4 * G2_STAGE)                   // 104448
#define G2_SLOTS (256 + 2 * NV * 2)               // 1088

__device__ __forceinline__ void g2_prefetch(uint32_t sb, int s, int qof, int pb, int t) {
#pragma unroll
    for (int i = 0; i < 5; i++) {
        int v = t + i * 256;
        if (v >= G2_SLOTS) break;
        if (v < 256) {
            int plane = v >> 7, r = (v >> 1) & 63, seg = v & 1;
            uint32_t sa = sb + (uint32_t)(s * G2_STAGE + plane * G2_APLANE + r * G2_RS + seg * 16);
            const uint32_t* xp = plane ? g_Xlo : g_Xhi;
            cp16(sa, (const char*)xp + ((size_t)(pb + r) * HW + qof) * 2 + seg * 16);
        } else {
            int v2 = v - 256;
            int plane = (v2 >= NV * 2) ? 1 : 0;
            int r = (v2 - plane * NV * 2) >> 1, seg = v2 & 1;
            uint32_t sa = sb + (uint32_t)(s * G2_STAGE + 2 * G2_APLANE + plane * G2_BPLANE + r * G2_RS + seg * 16);
            const __nv_bfloat16* vp = plane ? g_Vtlo : g_Vthi;
            cp16(sa, (const char*)vp + ((size_t)r * HW + qof + seg * 8) * 2);
        }
    }
}

__global__ void __launch_bounds__(256, 2) k_gemm2() {
    extern __shared__ char smem[];
    uint32_t sb = smem_u32(smem);
    int t = threadIdx.x, w = t >> 5, l = t & 31;
    int pb = blockIdx.x << 6;
    int q0 = blockIdx.y << 10;
    int wm = w & 3, wn = w >> 2;     // SMSP-balanced; wn0: 7 tiles, wn1: 6 tiles
    int nt = wn ? 6 : 7;

    float acc[14][4] = {};

    uint32_t arow = (uint32_t)((wm * 16 + (l & 15)) * G2_RS);
    uint32_t colb = (uint32_t)((l >> 4) << 4);

    g2_prefetch(sb, 0, q0, pb, t); CP_COMMIT;
    g2_prefetch(sb, 1, q0 + 16, pb, t); CP_COMMIT;
    g2_prefetch(sb, 2, q0 + 32, pb, t); CP_COMMIT;

    for (int kc = 0; kc < 64; kc++) {
        CP_WAIT2;
        __syncthreads();
        if (kc <= 60) g2_prefetch(sb, (kc + 3) & 3, q0 + (kc + 3) * 16, pb, t);
        CP_COMMIT;

        uint32_t baseA = sb + (uint32_t)((kc & 3) * G2_STAGE);
        uint32_t baseB = baseA + 2 * G2_APLANE;

        uint32_t ah[4], al[4];
        uint32_t ad = baseA + arow + colb;
        LDSM_X4(ah[0], ah[1], ah[2], ah[3], ad);
        LDSM_X4(al[0], al[1], al[2], al[3], ad + G2_APLANE);

        uint32_t bh[2][4], bl[2][4];
        {
            uint32_t bd = baseB + (uint32_t)((wn * 112 + (l & 15)) * G2_RS) + colb;
            LDSM_X4(bh[0][0], bh[0][1], bh[0][2], bh[0][3], bd);
            LDSM_X4(bl[0][0], bl[0][1], bl[0][2], bl[0][3], bd + G2_BPLANE);
        }
#pragma unroll
        for (int np = 0; np < 7; np++) {
            if (np < nt) {
                int cur = np & 1, nxt = cur ^ 1;
                if (np + 1 < nt) {
                    uint32_t bd = baseB + (uint32_t)((wn * 112 + (np + 1) * 16 + (l & 15)) * G2_RS) + colb;
                    LDSM_X4(bh[nxt][0], bh[nxt][1], bh[nxt][2], bh[nxt][3], bd);
                    LDSM_X4(bl[nxt][0], bl[nxt][1], bl[nxt][2], bl[nxt][3], bd + G2_BPLANE);
                }
                mma_bf16(acc[np * 2 + 0], ah, bh[cur][0], bh[cur][2]);
                mma_bf16(acc[np * 2 + 1], ah, bh[cur][1], bh[cur][3]);
                mma_bf16(acc[np * 2 + 0], ah, bl[cur][0], bl[cur][2]);
                mma_bf16(acc[np * 2 + 1], ah, bl[cur][1], bl[cur][3]);
                mma_bf16(acc[np * 2 + 0], al, bh[cur][0], bh[cur][2]);
                mma_bf16(acc[np * 2 + 1], al, bh[cur][1], bh[cur][3]);
            }
        }
    }

    // epilogue: fp32 partials
    int r0 = pb + wm * 16 + (l >> 2);
    int cb2 = (l & 3) * 2;
    float* Wp = g_Wpart + (size_t)blockIdx.y * HW * NV;
#pragma unroll
    for (int np = 0; np < 7; np++) {
        if (np < nt) {
#pragma unroll
            for (int n8 = 0; n8 < 2; n8++) {
                int col = wn * 112 + np * 16 + n8 * 8 + cb2;
                float* a = acc[np * 2 + n8];
                *(float2*)&Wp[(size_t)r0 * NV + col]       = make_float2(a[0], a[1]);
                *(float2*)&Wp[(size_t)(r0 + 8) * NV + col] = make_float2(a[2], a[3]);
            }
        }
    }
}

// ---------------- 8) combine (reads k-split partials directly) ----------------
__global__ void k_combine() {
    int idx = blockIdx.x * 256 + threadIdx.x;   // p*64 + c
    if (idx >= HW * CO) return;
    int p = idx >> 6, c = idx & 63;
    float comb = 0.f, msum = 0.f;
#pragma unroll
    for (int k = 0; k < 3; k++) {
        if (g_maskA[k * HW + p]) {
            msum += 1.f;
            float E = 0.f, Wv = 0.f;
#pragma unroll
            for (int ks = 0; ks < 4; ks++) {
                const float* Wp = g_Wpart + (size_t)ks * HW * NV + (size_t)p * NV;
                E  += Wp[192 + k];
                Wv += Wp[k * 64 + c];
            }
            float denom = E + (4096.0f - g_nbk[k]);
            comb += (Wv + g_U0[c] - g_Bk[k * CO + c]) / denom;
        }
    }
    g_aligned[idx] = comb / fmaxf(msum, 1.0f);
}

// ---------------- 9) bilinear upsample 64 -> 256, smem-staged coalesced ----------------
// grid = 256 (one block per output row Y), 256 threads.
// smem holds the y-interpolated row: 64 x-positions x 64 channels, [c][x] padded.
__global__ void __launch_bounds__(256) k_up(float* __restrict__ out) {
    __shared__ float sm[64 * 65];      // [c][x], stride 65
    int t = threadIdx.x;
    int Y = blockIdx.x;
    const float sc = 63.0f / 255.0f;
    float ry = (float)Y * sc;
    int y0 = (int)ry;
    int y1 = min(y0 + 1, 63);
    float wy = ry - (float)y0;

    // load rows y0,y1 of g_aligned ([pos][c], rows contiguous 16 KB) with y-interp folded
    const float* A0 = g_aligned + (size_t)(y0 << 6) * CO;
    const float* A1 = g_aligned + (size_t)(y1 << 6) * CO;
#pragma unroll
    for (int i = 0; i < 16; i++) {
        int v = t + i * 256;           // v < 4096 : x*64 + c
        int x = v >> 6, c = v & 63;
        float a = A0[v], b = A1[v];
        sm[c * 65 + x] = a + (b - a) * wy;
    }
    __syncthreads();

    // write 64 c x 256 X, coalesced in X
#pragma unroll
    for (int i = 0; i < 64; i++) {
        int v = t + i * 256;           // v < 16384 : c*256 + X
        int c = v >> 8, X = v & 255;
        float rx = (float)X * sc;
        int x0 = (int)rx;
        int x1 = min(x0 + 1, 63);
        float wx = rx - (float)x0;
        float a = sm[c * 65 + x0], b = sm[c * 65 + x1];
        out[(size_t)c * 65536 + Y * 256 + X] = a + (b - a) * wx;
    }
}

// ---------------- launch ----------------
extern "C" void kernel_launch(void* const* d_in, const int* in_sizes, int n_in,
                              void* d_out, int out_size) {
    const float* ufb_in = (const float*)d_in[0];   // (1,64,256,256)
    const float* fa     = (const float*)d_in[1];   // (1,256,64,64)
    const int*   fap    = (const int*)  d_in[2];   // (1,4,256,256)
    const float* fb     = (const float*)d_in[3];   // (1,256,64,64)
    const int*   fbp    = (const int*)  d_in[4];   // (1,4,256,256)
    float* out = (float*)d_out;                    // (1,64,256,256)

    cudaFuncSetAttribute(k_gemm_mma, cudaFuncAttributeMaxDynamicSharedMemorySize, G1_SMEM);
    cudaFuncSetAttribute(k_gemm2,    cudaFuncAttributeMaxDynamicSharedMemorySize, G2_SMEM);

    k_masks<<<16, 256>>>(fap, fbp);
    k_mean<<<512, 256>>>(fa, fb);
    k_norm<<<dim3(128, 2), 256>>>(fa, fb);
    k_gemm_mma<<<dim3(32, 32), 256, G1_SMEM>>>();          // 4th launch -> profiled
    k_ufb<<<(HW * CO) / 256, 256>>>(ufb_in);
    k_ub<<<64, 256>>>();
    k_V<<<(NV * HW) / 256, 256>>>();
    k_gemm2<<<dim3(64, 4), 256, G2_SMEM>>>();
    k_combine<<<(HW * CO) / 256, 256>>>();
    k_up<<<256, 256>>>(out);
}

// round 11
// speedup vs baseline: 1.2401x; 1.1801x over previous
#include <cuda_runtime.h>
#include <cuda_bf16.h>
#include <math.h>
#include <stdint.h>

#define HW 4096         // 64*64 spatial positions at feature res
#define CF 256          // feature channels
#define CO 64           // value channels (unalign_fb)
#define ALPHA 100.0f
#define NV 208          // GEMM2 cols: 3*64 warped + 3 E + 13 pad (13 n16 tiles)

// ---------------- device scratch (allocation-free) ----------------
__device__ uint32_t g_Xhi[(size_t)HW * HW / 2]; // bf16x2 hi plane (q,q+1)
__device__ uint32_t g_Xlo[(size_t)HW * HW / 2]; // bf16x2 lo plane
__device__ __nv_bfloat16 g_faHi[HW * CF];
__device__ __nv_bfloat16 g_faLo[HW * CF];
__device__ __nv_bfloat16 g_fbHi[HW * CF];
__device__ __nv_bfloat16 g_fbLo[HW * CF];
__device__ __nv_bfloat16 g_Vthi[NV * HW];    // V^T [col][q]
__device__ __nv_bfloat16 g_Vtlo[NV * HW];
__device__ float g_Wpart[4 * HW * NV];       // GEMM2 k-split partials
__device__ float g_ufb[HW * CO];             // downsampled values, [q][c]
__device__ float g_meanA[CF];
__device__ float g_meanB[CF];
__device__ unsigned char g_maskA[3 * HW];
__device__ unsigned char g_codeB[HW];        // 3-bit code of mask_b per q
__device__ float g_U0[CO];                   // sum_q ufb[q][c]
__device__ float g_Bk[3 * CO];               // B_k[c] = sum_{q in mb_k} ufb[q][c]
__device__ float g_nbk[3];                   // |mb_k|
__device__ float g_aligned[HW * CO];         // [p][c]

// ---------------- helpers ----------------
__device__ __forceinline__ uint32_t smem_u32(const void* p) {
    uint32_t a;
    asm("{ .reg .u64 t; cvta.to.shared.u64 t, %1; cvt.u32.u64 %0, t; }" : "=r"(a) : "l"(p));
    return a;
}

#define LDSM_X4(r0, r1, r2, r3, addr) \
    asm volatile("ldmatrix.sync.aligned.m8n8.x4.shared.b16 {%0,%1,%2,%3}, [%4];" \
        : "=r"(r0), "=r"(r1), "=r"(r2), "=r"(r3) : "r"(addr))

__device__ __forceinline__ void mma_bf16(float* c, const uint32_t* a, uint32_t b0, uint32_t b1) {
    asm volatile(
        "mma.sync.aligned.m16n8k16.row.col.f32.bf16.bf16.f32 "
        "{%0,%1,%2,%3}, {%4,%5,%6,%7}, {%8,%9}, {%0,%1,%2,%3};"
        : "+f"(c[0]), "+f"(c[1]), "+f"(c[2]), "+f"(c[3])
        : "r"(a[0]), "r"(a[1]), "r"(a[2]), "r"(a[3]), "r"(b0), "r"(b1));
}

__device__ __forceinline__ void cp16(uint32_t saddr, const void* g) {
    asm volatile("cp.async.cg.shared.global [%0], [%1], 16;" :: "r"(saddr), "l"(g));
}
#define CP_COMMIT asm volatile("cp.async.commit_group;" ::: "memory")
#define CP_WAIT0  asm volatile("cp.async.wait_group 0;" ::: "memory")
#define CP_WAIT1  asm volatile("cp.async.wait_group 1;" ::: "memory")
#define CP_WAIT2  asm volatile("cp.async.wait_group 2;" ::: "memory")

// ---------------- 1) masks ----------------
__global__ void k_masks(const int* __restrict__ fap, const int* __restrict__ fbp) {
    int p = blockIdx.x * 256 + threadIdx.x;
    if (p >= HW) return;
    int y = (p >> 6) << 2, x = (p & 63) << 2;
    int off = y * 256 + x;
    unsigned code = 0;
#pragma unroll
    for (int k = 0; k < 3; k++) {
        g_maskA[k * HW + p] = (fap[(k + 1) * 65536 + off] != 0) ? 1 : 0;
        if (fbp[(k + 1) * 65536 + off] != 0) code |= (1u << k);
    }
    g_codeB[p] = (unsigned char)code;
}

// ---------------- 2) per-channel spatial means ----------------
__global__ void k_mean(const float* __restrict__ fa, const float* __restrict__ fb) {
    int cb = blockIdx.x;
    int ch = cb & 255;
    const float* src = (cb < 256) ? fa : fb;
    float s = 0.f;
    for (int i = threadIdx.x; i < HW; i += 256) s += src[ch * HW + i];
    __shared__ float red[256];
    red[threadIdx.x] = s;
    __syncthreads();
    for (int st = 128; st > 0; st >>= 1) {
        if (threadIdx.x < st) red[threadIdx.x] += red[threadIdx.x + st];
        __syncthreads();
    }
    if (threadIdx.x == 0) {
        float m = red[0] / (float)HW;
        if (cb < 256) g_meanA[ch] = m; else g_meanB[ch] = m;
    }
}

// ---------------- 3) center + normalize + split, smem-transposed ----------------
__global__ void __launch_bounds__(256) k_norm(const float* __restrict__ fa,
                                              const float* __restrict__ fb) {
    __shared__ float sm[256 * 33];
    int t = threadIdx.x;
    int pb = blockIdx.x * 32;
    const float* src;  const float* mean;
    __nv_bfloat16 *dHi, *dLo;
    if (blockIdx.y == 0) { src = fa; mean = g_meanA; dHi = g_faHi; dLo = g_faLo; }
    else                 { src = fb; mean = g_meanB; dHi = g_fbHi; dLo = g_fbLo; }

#pragma unroll
    for (int i = 0; i < 32; i++) {
        int v = t + i * 256;
        int c = v >> 5, p = v & 31;
        sm[c * 33 + p] = src[c * HW + pb + p] - mean[c];
    }
    __syncthreads();

    int p = t >> 3, part = t & 7;
    float nsq = 0.f;
#pragma unroll
    for (int j = 0; j < 32; j++) {
        int c = part * 32 + ((j + part * 4) & 31);
        float v = sm[c * 33 + p];
        nsq += v * v;
    }
    nsq += __shfl_xor_sync(0xFFFFFFFF, nsq, 1);
    nsq += __shfl_xor_sync(0xFFFFFFFF, nsq, 2);
    nsq += __shfl_xor_sync(0xFFFFFFFF, nsq, 4);
    float inv = rsqrtf(nsq);

    size_t base = ((size_t)(pb + p) * CF + part * 32);
    uint32_t* hdst = (uint32_t*)(dHi + base);
    uint32_t* ldst = (uint32_t*)(dLo + base);
#pragma unroll
    for (int j = 0; j < 16; j++) {
        int c = part * 32 + j * 2;
        float v0 = sm[(c + 0) * 33 + p] * inv;
        float v1 = sm[(c + 1) * 33 + p] * inv;
        __nv_bfloat16 h0 = __float2bfloat16(v0), h1 = __float2bfloat16(v1);
        __nv_bfloat162 hp; hp.x = h0; hp.y = h1;
        __nv_bfloat16 l0 = __float2bfloat16(v0 - __bfloat162float(h0));
        __nv_bfloat16 l1 = __float2bfloat16(v1 - __bfloat162float(h1));
        __nv_bfloat162 lp; lp.x = l0; lp.y = l1;
        hdst[j] = *(uint32_t*)&hp;
        ldst[j] = *(uint32_t*)&lp;
    }
}

// ---------------- 4) bilinear downsample 256->64 ----------------
__global__ void k_ufb(const float* __restrict__ ub) {
    int idx = blockIdx.x * 256 + threadIdx.x;
    if (idx >= HW * CO) return;
    int c = idx & 63, q = idx >> 6;
    int i = q >> 6, j = q & 63;
    const float sc = 255.0f / 63.0f;
    float ry = (float)i * sc, rx = (float)j * sc;
    int y0 = (int)ry, x0 = (int)rx;
    int y1 = min(y0 + 1, 255), x1 = min(x0 + 1, 255);
    float wy = ry - (float)y0, wx = rx - (float)x0;
    const float* b = ub + c * 65536;
    float v00 = b[y0 * 256 + x0], v01 = b[y0 * 256 + x1];
    float v10 = b[y1 * 256 + x0], v11 = b[y1 * 256 + x1];
    float r0 = v00 * (1.f - wy) + v10 * wy;
    float r1 = v01 * (1.f - wy) + v11 * wy;
    g_ufb[q * CO + c] = r0 * (1.f - wx) + r1 * wx;
}

// ---------------- 5) U0[c], Bk[k][c], nbk ----------------
__global__ void k_ub() {
    int c = blockIdx.x;
    __shared__ float s_acc[4];
    __shared__ int   s_n[3];
    if (threadIdx.x < 4) s_acc[threadIdx.x] = 0.f;
    if (threadIdx.x < 3) s_n[threadIdx.x] = 0;
    __syncthreads();
    float a0 = 0, b0 = 0, b1 = 0, b2 = 0;
    int n0 = 0, n1 = 0, n2 = 0;
    for (int q = threadIdx.x; q < HW; q += 256) {
        float u = g_ufb[q * CO + c];
        int code = g_codeB[q];
        a0 += u;
        if (code & 1) { b0 += u; n0++; }
        if (code & 2) { b1 += u; n1++; }
        if (code & 4) { b2 += u; n2++; }
    }
    atomicAdd(&s_acc[0], a0);
    atomicAdd(&s_acc[1], b0);
    atomicAdd(&s_acc[2], b1);
    atomicAdd(&s_acc[3], b2);
    if (c == 0) {
        atomicAdd(&s_n[0], n0); atomicAdd(&s_n[1], n1); atomicAdd(&s_n[2], n2);
    }
    __syncthreads();
    if (threadIdx.x == 0) g_U0[c] = s_acc[0];
    if (threadIdx.x < 3) {
        g_Bk[threadIdx.x * CO + c] = s_acc[1 + threadIdx.x];
        if (c == 0) g_nbk[threadIdx.x] = (float)s_n[threadIdx.x];
    }
}

// ---------------- 5b) build V^T planes ----------------
__global__ void k_V() {
    int idx = blockIdx.x * 256 + threadIdx.x;
    if (idx >= NV * HW) return;
    int col = idx >> 12, q = idx & 4095;
    float v = 0.f;
    int code = g_codeB[q];
    if (col < 192) {
        int k = col >> 6, c = col & 63;
        v = ((code >> k) & 1) ? g_ufb[q * CO + c] : 0.f;
    } else if (col < 195) {
        v = (float)((code >> (col - 192)) & 1);
    }
    __nv_bfloat16 h = __float2bfloat16(v);
    g_Vthi[idx] = h;
    g_Vtlo[idx] = __float2bfloat16(v - __bfloat162float(h));
}

// ---------------- 6) GEMM1: split-bf16, 128x128, 2-stage k32 (best measured) ----------------
#define G1_PLANE 10240              // 128 rows * 80 bytes
#define G1_SMEM  (2 * 4 * G1_PLANE) // 81920

__device__ __forceinline__ void g1_prefetch(uint32_t sb, int buf, int kc,
                                            int pb, int qb, int t) {
    int kof = kc * 32;
#pragma unroll
    for (int i = 0; i < 8; i++) {
        int v = t + i * 256;
        int plane = v >> 9, r = (v >> 2) & 127, seg = v & 3;
        uint32_t sa = sb + (uint32_t)(buf * (4 * G1_PLANE) + plane * G1_PLANE + r * 80 + seg * 16);
        const __nv_bfloat16* src = (plane == 0) ? g_faHi : (plane == 1) ? g_faLo
                                 : (plane == 2) ? g_fbHi : g_fbLo;
        int rowb = (plane < 2) ? pb : qb;
        cp16(sa, (const char*)src + ((size_t)(rowb + r) * CF + kof + seg * 8) * 2);
    }
}

__global__ void __launch_bounds__(256, 2) k_gemm_mma() {
    extern __shared__ char smem[];
    uint32_t sb = smem_u32(smem);
    int t = threadIdx.x, w = t >> 5, l = t & 31;
    int qb = blockIdx.x << 7, pb = blockIdx.y << 7;
    int wm = w >> 1, wn = w & 1;

    float acc[2][8][4] = {};

    int rowA = wm * 32 + (l & 15);
    int rowB = wn * 64 + (l & 15);
    uint32_t colb = (uint32_t)((l >> 4) << 4);

    g1_prefetch(sb, 0, 0, pb, qb, t); CP_COMMIT;

    for (int kc = 0; kc < 8; kc++) {
        if (kc < 7) { g1_prefetch(sb, (kc + 1) & 1, kc + 1, pb, qb, t); CP_COMMIT; CP_WAIT1; }
        else CP_WAIT0;
        __syncthreads();

        uint32_t baseA = sb + (uint32_t)((kc & 1) * (4 * G1_PLANE));
        uint32_t baseB = baseA + 2 * G1_PLANE;

#pragma unroll
        for (int kk2 = 0; kk2 < 2; kk2++) {
            uint32_t kb = (uint32_t)(kk2 * 32) + colb;
            uint32_t ah[2][4], al[2][4];
#pragma unroll
            for (int mi = 0; mi < 2; mi++) {
                uint32_t ad = baseA + (uint32_t)((rowA + mi * 16) * 80) + kb;
                LDSM_X4(ah[mi][0], ah[mi][1], ah[mi][2], ah[mi][3], ad);
                LDSM_X4(al[mi][0], al[mi][1], al[mi][2], al[mi][3], ad + G1_PLANE);
            }
#pragma unroll
            for (int np = 0; np < 4; np++) {
                uint32_t bd = baseB + (uint32_t)((rowB + np * 16) * 80) + kb;
                uint32_t bh[4], bl[4];
                LDSM_X4(bh[0], bh[1], bh[2], bh[3], bd);
                LDSM_X4(bl[0], bl[1], bl[2], bl[3], bd + G1_PLANE);
                mma_bf16(acc[0][np * 2 + 0], ah[0], bh[0], bh[2]);
                mma_bf16(acc[0][np * 2 + 1], ah[0], bh[1], bh[3]);
                mma_bf16(acc[1][np * 2 + 0], ah[1], bh[0], bh[2]);
                mma_bf16(acc[1][np * 2 + 1], ah[1], bh[1], bh[3]);
                mma_bf16(acc[0][np * 2 + 0], ah[0], bl[0], bl[2]);
                mma_bf16(acc[0][np * 2 + 1], ah[0], bl[1], bl[3]);
                mma_bf16(acc[1][np * 2 + 0], ah[1], bl[0], bl[2]);
                mma_bf16(acc[1][np * 2 + 1], ah[1], bl[1], bl[3]);
                mma_bf16(acc[0][np * 2 + 0], al[0], bh[0], bh[2]);
                mma_bf16(acc[0][np * 2 + 1], al[0], bh[1], bh[3]);
                mma_bf16(acc[1][np * 2 + 0], al[1], bh[0], bh[2]);
                mma_bf16(acc[1][np * 2 + 1], al[1], bh[1], bh[3]);
            }
        }
        __syncthreads();
    }

    // ---- epilogue: exp + bf16 hi/lo plane stores ----
    int prl = wm * 32 + (l >> 2);
    int qcl = wn * 64 + (l & 3) * 2;
#pragma unroll
    for (int mi = 0; mi < 2; mi++) {
#pragma unroll
        for (int nj = 0; nj < 8; nj++) {
#pragma unroll
            for (int half = 0; half < 2; half++) {
                int rloc = prl + mi * 16 + half * 8;
                int qloc = qcl + nj * 8;
                float x0 = __expf(fminf(ALPHA * acc[mi][nj][half * 2 + 0], 80.f));
                float x1 = __expf(fminf(ALPHA * acc[mi][nj][half * 2 + 1], 80.f));
                __nv_bfloat16 h0 = __float2bfloat16(x0);
                __nv_bfloat16 h1 = __float2bfloat16(x1);
                __nv_bfloat16 lo0 = __float2bfloat16(x0 - __bfloat162float(h0));
                __nv_bfloat16 lo1 = __float2bfloat16(x1 - __bfloat162float(h1));
                __nv_bfloat162 hp; hp.x = h0; hp.y = h1;
                __nv_bfloat162 lp; lp.x = lo0; lp.y = lo1;
                size_t idx = ((size_t)(pb + rloc) * HW + qb + qloc) >> 1;
                g_Xhi[idx] = *(uint32_t*)&hp;
                g_Xlo[idx] = *(uint32_t*)&lp;
            }
        }
    }
}

// ---------------- 7) GEMM2: W = X @ V^T, 4-stage k16 pipeline ----------------
#define G2_RS 48
#define G2_APLANE (64 * G2_RS)
#define G2_BPLANE (NV * G2_RS)
#define G2_STAGE (2 * G2_APLANE + 2 * G2_BPLANE)
#define G2_SMEM  (4 * G2_STAGE)
#define G2_SLOTS (256 + 2 * NV * 2)

__device__ __forceinline__ void g2_prefetch(uint32_t sb, int s, int qof, int pb, int t) {
#pragma unroll
    for (int i = 0; i < 5; i++) {
        int v = t + i * 256;
        if (v >= G2_SLOTS) break;
        if (v < 256) {
            int plane = v >> 7, r = (v >> 1) & 63, seg = v & 1;
            uint32_t sa = sb + (uint32_t)(s * G2_STAGE + plane * G2_APLANE + r * G2_RS + seg * 16);
            const uint32_t* xp = plane ? g_Xlo : g_Xhi;
            cp16(sa, (const char*)xp + ((size_t)(pb + r) * HW + qof) * 2 + seg * 16);
        } else {
            int v2 = v - 256;
            int plane = (v2 >= NV * 2) ? 1 : 0;
            int r = (v2 - plane * NV * 2) >> 1, seg = v2 & 1;
            uint32_t sa = sb + (uint32_t)(s * G2_STAGE + 2 * G2_APLANE + plane * G2_BPLANE + r * G2_RS + seg * 16);
            const __nv_bfloat16* vp = plane ? g_Vtlo : g_Vthi;
            cp16(sa, (const char*)vp + ((size_t)r * HW + qof + seg * 8) * 2);
        }
    }
}

__global__ void __launch_bounds__(256, 2) k_gemm2() {
    extern __shared__ char smem[];
    uint32_t sb = smem_u32(smem);
    int t = threadIdx.x, w = t >> 5, l = t & 31;
    int pb = blockIdx.x << 6;
    int q0 = blockIdx.y << 10;
    int wm = w & 3, wn = w >> 2;
    int nt = wn ? 6 : 7;

    float acc[14][4] = {};

    uint32_t arow = (uint32_t)((wm * 16 + (l & 15)) * G2_RS);
    uint32_t colb = (uint32_t)((l >> 4) << 4);

    g2_prefetch(sb, 0, q0, pb, t); CP_COMMIT;
    g2_prefetch(sb, 1, q0 + 16, pb, t); CP_COMMIT;
    g2_prefetch(sb, 2, q0 + 32, pb, t); CP_COMMIT;

    for (int kc = 0; kc < 64; kc++) {
        CP_WAIT2;
        __syncthreads();
        if (kc <= 60) g2_prefetch(sb, (kc + 3) & 3, q0 + (kc + 3) * 16, pb, t);
        CP_COMMIT;

        uint32_t baseA = sb + (uint32_t)((kc & 3) * G2_STAGE);
        uint32_t baseB = baseA + 2 * G2_APLANE;

        uint32_t ah[4], al[4];
        uint32_t ad = baseA + arow + colb;
        LDSM_X4(ah[0], ah[1], ah[2], ah[3], ad);
        LDSM_X4(al[0], al[1], al[2], al[3], ad + G2_APLANE);

        uint32_t bh[2][4], bl[2][4];
        {
            uint32_t bd = baseB + (uint32_t)((wn * 112 + (l & 15)) * G2_RS) + colb;
            LDSM_X4(bh[0][0], bh[0][1], bh[0][2], bh[0][3], bd);
            LDSM_X4(bl[0][0], bl[0][1], bl[0][2], bl[0][3], bd + G2_BPLANE);
        }
#pragma unroll
        for (int np = 0; np < 7; np++) {
            if (np < nt) {
                int cur = np & 1, nxt = cur ^ 1;
                if (np + 1 < nt) {
                    uint32_t bd = baseB + (uint32_t)((wn * 112 + (np + 1) * 16 + (l & 15)) * G2_RS) + colb;
                    LDSM_X4(bh[nxt][0], bh[nxt][1], bh[nxt][2], bh[nxt][3], bd);
                    LDSM_X4(bl[nxt][0], bl[nxt][1], bl[nxt][2], bl[nxt][3], bd + G2_BPLANE);
                }
                mma_bf16(acc[np * 2 + 0], ah, bh[cur][0], bh[cur][2]);
                mma_bf16(acc[np * 2 + 1], ah, bh[cur][1], bh[cur][3]);
                mma_bf16(acc[np * 2 + 0], ah, bl[cur][0], bl[cur][2]);
                mma_bf16(acc[np * 2 + 1], ah, bl[cur][1], bl[cur][3]);
                mma_bf16(acc[np * 2 + 0], al, bh[cur][0], bh[cur][2]);
                mma_bf16(acc[np * 2 + 1], al, bh[cur][1], bh[cur][3]);
            }
        }
    }

    int r0 = pb + wm * 16 + (l >> 2);
    int cb2 = (l & 3) * 2;
    float* Wp = g_Wpart + (size_t)blockIdx.y * HW * NV;
#pragma unroll
    for (int np = 0; np < 7; np++) {
        if (np < nt) {
#pragma unroll
            for (int n8 = 0; n8 < 2; n8++) {
                int col = wn * 112 + np * 16 + n8 * 8 + cb2;
                float* a = acc[np * 2 + n8];
                *(float2*)&Wp[(size_t)r0 * NV + col]       = make_float2(a[0], a[1]);
                *(float2*)&Wp[(size_t)(r0 + 8) * NV + col] = make_float2(a[2], a[3]);
            }
        }
    }
}

// ---------------- 8) combine (reads k-split partials directly) ----------------
__global__ void k_combine() {
    int idx = blockIdx.x * 256 + threadIdx.x;
    if (idx >= HW * CO) return;
    int p = idx >> 6, c = idx & 63;
    float comb = 0.f, msum = 0.f;
#pragma unroll
    for (int k = 0; k < 3; k++) {
        if (g_maskA[k * HW + p]) {
            msum += 1.f;
            float E = 0.f, Wv = 0.f;
#pragma unroll
            for (int ks = 0; ks < 4; ks++) {
                const float* Wp = g_Wpart + (size_t)ks * HW * NV + (size_t)p * NV;
                E  += Wp[192 + k];
                Wv += Wp[k * 64 + c];
            }
            float denom = E + (4096.0f - g_nbk[k]);
            comb += (Wv + g_U0[c] - g_Bk[k * CO + c]) / denom;
        }
    }
    g_aligned[idx] = comb / fmaxf(msum, 1.0f);
}

// ---------------- 9) bilinear upsample 64 -> 256, smem-staged coalesced ----------------
__global__ void __launch_bounds__(256) k_up(float* __restrict__ out) {
    __shared__ float sm[64 * 65];
    int t = threadIdx.x;
    int Y = blockIdx.x;
    const float sc = 63.0f / 255.0f;
    float ry = (float)Y * sc;
    int y0 = (int)ry;
    int y1 = min(y0 + 1, 63);
    float wy = ry - (float)y0;

    const float* A0 = g_aligned + (size_t)(y0 << 6) * CO;
    const float* A1 = g_aligned + (size_t)(y1 << 6) * CO;
#pragma unroll
    for (int i = 0; i < 16; i++) {
        int v = t + i * 256;
        int x = v >> 6, c = v & 63;
        float a = A0[v], b = A1[v];
        sm[c * 65 + x] = a + (b - a) * wy;
    }
    __syncthreads();

#pragma unroll
    for (int i = 0; i < 64; i++) {
        int v = t + i * 256;
        int c = v >> 8, X = v & 255;
        float rx = (float)X * sc;
        int x0 = (int)rx;
        int x1 = min(x0 + 1, 63);
        float wx = rx - (float)x0;
        float a = sm[c * 65 + x0], b = sm[c * 65 + x1];
        out[(size_t)c * 65536 + Y * 256 + X] = a + (b - a) * wx;
    }
}

// ---------------- launch ----------------
extern "C" void kernel_launch(void* const* d_in, const int* in_sizes, int n_in,
                              void* d_out, int out_size) {
    const float* ufb_in = (const float*)d_in[0];   // (1,64,256,256)
    const float* fa     = (const float*)d_in[1];   // (1,256,64,64)
    const int*   fap    = (const int*)  d_in[2];   // (1,4,256,256)
    const float* fb     = (const float*)d_in[3];   // (1,256,64,64)
    const int*   fbp    = (const int*)  d_in[4];   // (1,4,256,256)
    float* out = (float*)d_out;                    // (1,64,256,256)

    static cudaStream_t s1 = nullptr;
    static cudaEvent_t e0 = nullptr, e1 = nullptr;
    if (!s1) {
        cudaStreamCreateWithFlags(&s1, cudaStreamNonBlocking);
        cudaEventCreateWithFlags(&e0, cudaEventDisableTiming);
        cudaEventCreateWithFlags(&e1, cudaEventDisableTiming);
        cudaFuncSetAttribute(k_gemm_mma, cudaFuncAttributeMaxDynamicSharedMemorySize, G1_SMEM);
        cudaFuncSetAttribute(k_gemm2,    cudaFuncAttributeMaxDynamicSharedMemorySize, G2_SMEM);
    }

    // fork: side stream handles the value/mask prep chain (independent of GEMM1)
    cudaEventRecord(e0, 0);
    cudaStreamWaitEvent(s1, e0, 0);

    k_mean<<<512, 256>>>(fa, fb);                          // 1 (s0)
    k_norm<<<dim3(128, 2), 256>>>(fa, fb);                 // 2 (s0)
    k_masks<<<16, 256, 0, s1>>>(fap, fbp);                 // 3 (s1)
    k_gemm_mma<<<dim3(32, 32), 256, G1_SMEM>>>();          // 4 (s0) -> profiled
    k_ufb<<<(HW * CO) / 256, 256, 0, s1>>>(ufb_in);        // 5 (s1, overlaps GEMM1)
    k_ub<<<64, 256, 0, s1>>>();                            // 6 (s1)
    k_V<<<(NV * HW) / 256, 256, 0, s1>>>();                // 7 (s1)
    cudaEventRecord(e1, s1);
    cudaStreamWaitEvent(0, e1, 0);                         // join before GEMM2

    k_gemm2<<<dim3(64, 4), 256, G2_SMEM>>>();
    k_combine<<<(HW * CO) / 256, 256>>>();
    k_up<<<256, 256>>>(out);
}

// round 12
// speedup vs baseline: 1.2570x; 1.0136x over previous
#include <cuda_runtime.h>
#include <cuda_bf16.h>
#include <math.h>
#include <stdint.h>

#define HW 4096         // 64*64 spatial positions at feature res
#define CF 256          // feature channels
#define CO 64           // value channels (unalign_fb)
#define ALPHA 100.0f
#define NV 208          // GEMM2 cols: 3*64 warped + 3 E + 13 pad (13 n16 tiles)
#define KSPLIT 8        // GEMM2 k-split planes

// ---------------- device scratch (allocation-free) ----------------
__device__ uint32_t g_Xhi[(size_t)HW * HW / 2]; // bf16x2 hi plane (q,q+1)
__device__ uint32_t g_Xlo[(size_t)HW * HW / 2]; // bf16x2 lo plane
__device__ __nv_bfloat16 g_faHi[HW * CF];
__device__ __nv_bfloat16 g_faLo[HW * CF];
__device__ __nv_bfloat16 g_fbHi[HW * CF];
__device__ __nv_bfloat16 g_fbLo[HW * CF];
__device__ __nv_bfloat16 g_Vthi[NV * HW];    // V^T [col][q]
__device__ __nv_bfloat16 g_Vtlo[NV * HW];
__device__ float g_Wpart[KSPLIT * HW * NV];  // GEMM2 k-split partials
__device__ float g_ufb[HW * CO];             // downsampled values, [q][c]
__device__ float g_meanA[CF];
__device__ float g_meanB[CF];
__device__ unsigned char g_maskA[3 * HW];
__device__ unsigned char g_codeB[HW];        // 3-bit code of mask_b per q
__device__ float g_U0[CO];                   // sum_q ufb[q][c]
__device__ float g_Bk[3 * CO];               // B_k[c] = sum_{q in mb_k} ufb[q][c]
__device__ float g_nbk[3];                   // |mb_k|
__device__ float g_aligned[HW * CO];         // [p][c]

// ---------------- helpers ----------------
__device__ __forceinline__ uint32_t smem_u32(const void* p) {
    uint32_t a;
    asm("{ .reg .u64 t; cvta.to.shared.u64 t, %1; cvt.u32.u64 %0, t; }" : "=r"(a) : "l"(p));
    return a;
}

#define LDSM_X4(r0, r1, r2, r3, addr) \
    asm volatile("ldmatrix.sync.aligned.m8n8.x4.shared.b16 {%0,%1,%2,%3}, [%4];" \
        : "=r"(r0), "=r"(r1), "=r"(r2), "=r"(r3) : "r"(addr))

__device__ __forceinline__ void mma_bf16(float* c, const uint32_t* a, uint32_t b0, uint32_t b1) {
    asm volatile(
        "mma.sync.aligned.m16n8k16.row.col.f32.bf16.bf16.f32 "
        "{%0,%1,%2,%3}, {%4,%5,%6,%7}, {%8,%9}, {%0,%1,%2,%3};"
        : "+f"(c[0]), "+f"(c[1]), "+f"(c[2]), "+f"(c[3])
        : "r"(a[0]), "r"(a[1]), "r"(a[2]), "r"(a[3]), "r"(b0), "r"(b1));
}

__device__ __forceinline__ void cp16(uint32_t saddr, const void* g) {
    asm volatile("cp.async.cg.shared.global [%0], [%1], 16;" :: "r"(saddr), "l"(g));
}
#define CP_COMMIT asm volatile("cp.async.commit_group;" ::: "memory")
#define CP_WAIT0  asm volatile("cp.async.wait_group 0;" ::: "memory")
#define CP_WAIT1  asm volatile("cp.async.wait_group 1;" ::: "memory")
#define CP_WAIT2  asm volatile("cp.async.wait_group 2;" ::: "memory")

// ---------------- 1) masks ----------------
__global__ void k_masks(const int* __restrict__ fap, const int* __restrict__ fbp) {
    int p = blockIdx.x * 256 + threadIdx.x;
    if (p >= HW) return;
    int y = (p >> 6) << 2, x = (p & 63) << 2;
    int off = y * 256 + x;
    unsigned code = 0;
#pragma unroll
    for (int k = 0; k < 3; k++) {
        g_maskA[k * HW + p] = (fap[(k + 1) * 65536 + off] != 0) ? 1 : 0;
        if (fbp[(k + 1) * 65536 + off] != 0) code |= (1u << k);
    }
    g_codeB[p] = (unsigned char)code;
}

// ---------------- 2) per-channel spatial means ----------------
__global__ void k_mean(const float* __restrict__ fa, const float* __restrict__ fb) {
    int cb = blockIdx.x;
    int ch = cb & 255;
    const float* src = (cb < 256) ? fa : fb;
    float s = 0.f;
    for (int i = threadIdx.x; i < HW; i += 256) s += src[ch * HW + i];
    __shared__ float red[256];
    red[threadIdx.x] = s;
    __syncthreads();
    for (int st = 128; st > 0; st >>= 1) {
        if (threadIdx.x < st) red[threadIdx.x] += red[threadIdx.x + st];
        __syncthreads();
    }
    if (threadIdx.x == 0) {
        float m = red[0] / (float)HW;
        if (cb < 256) g_meanA[ch] = m; else g_meanB[ch] = m;
    }
}

// ---------------- 3) center + normalize + split, smem-transposed ----------------
__global__ void __launch_bounds__(256) k_norm(const float* __restrict__ fa,
                                              const float* __restrict__ fb) {
    __shared__ float sm[256 * 33];
    int t = threadIdx.x;
    int pb = blockIdx.x * 32;
    const float* src;  const float* mean;
    __nv_bfloat16 *dHi, *dLo;
    if (blockIdx.y == 0) { src = fa; mean = g_meanA; dHi = g_faHi; dLo = g_faLo; }
    else                 { src = fb; mean = g_meanB; dHi = g_fbHi; dLo = g_fbLo; }

#pragma unroll
    for (int i = 0; i < 32; i++) {
        int v = t + i * 256;
        int c = v >> 5, p = v & 31;
        sm[c * 33 + p] = src[c * HW + pb + p] - mean[c];
    }
    __syncthreads();

    int p = t >> 3, part = t & 7;
    float nsq = 0.f;
#pragma unroll
    for (int j = 0; j < 32; j++) {
        int c = part * 32 + ((j + part * 4) & 31);
        float v = sm[c * 33 + p];
        nsq += v * v;
    }
    nsq += __shfl_xor_sync(0xFFFFFFFF, nsq, 1);
    nsq += __shfl_xor_sync(0xFFFFFFFF, nsq, 2);
    nsq += __shfl_xor_sync(0xFFFFFFFF, nsq, 4);
    float inv = rsqrtf(nsq);

    size_t base = ((size_t)(pb + p) * CF + part * 32);
    uint32_t* hdst = (uint32_t*)(dHi + base);
    uint32_t* ldst = (uint32_t*)(dLo + base);
#pragma unroll
    for (int j = 0; j < 16; j++) {
        int c = part * 32 + j * 2;
        float v0 = sm[(c + 0) * 33 + p] * inv;
        float v1 = sm[(c + 1) * 33 + p] * inv;
        __nv_bfloat16 h0 = __float2bfloat16(v0), h1 = __float2bfloat16(v1);
        __nv_bfloat162 hp; hp.x = h0; hp.y = h1;
        __nv_bfloat16 l0 = __float2bfloat16(v0 - __bfloat162float(h0));
        __nv_bfloat16 l1 = __float2bfloat16(v1 - __bfloat162float(h1));
        __nv_bfloat162 lp; lp.x = l0; lp.y = l1;
        hdst[j] = *(uint32_t*)&hp;
        ldst[j] = *(uint32_t*)&lp;
    }
}

// ---------------- 4) bilinear downsample 256->64 ----------------
__global__ void k_ufb(const float* __restrict__ ub) {
    int idx = blockIdx.x * 256 + threadIdx.x;
    if (idx >= HW * CO) return;
    int c = idx & 63, q = idx >> 6;
    int i = q >> 6, j = q & 63;
    const float sc = 255.0f / 63.0f;
    float ry = (float)i * sc, rx = (float)j * sc;
    int y0 = (int)ry, x0 = (int)rx;
    int y1 = min(y0 + 1, 255), x1 = min(x0 + 1, 255);
    float wy = ry - (float)y0, wx = rx - (float)x0;
    const float* b = ub + c * 65536;
    float v00 = b[y0 * 256 + x0], v01 = b[y0 * 256 + x1];
    float v10 = b[y1 * 256 + x0], v11 = b[y1 * 256 + x1];
    float r0 = v00 * (1.f - wy) + v10 * wy;
    float r1 = v01 * (1.f - wy) + v11 * wy;
    g_ufb[q * CO + c] = r0 * (1.f - wx) + r1 * wx;
}

// ---------------- 5) U0[c], Bk[k][c], nbk ----------------
__global__ void k_ub() {
    int c = blockIdx.x;
    __shared__ float s_acc[4];
    __shared__ int   s_n[3];
    if (threadIdx.x < 4) s_acc[threadIdx.x] = 0.f;
    if (threadIdx.x < 3) s_n[threadIdx.x] = 0;
    __syncthreads();
    float a0 = 0, b0 = 0, b1 = 0, b2 = 0;
    int n0 = 0, n1 = 0, n2 = 0;
    for (int q = threadIdx.x; q < HW; q += 256) {
        float u = g_ufb[q * CO + c];
        int code = g_codeB[q];
        a0 += u;
        if (code & 1) { b0 += u; n0++; }
        if (code & 2) { b1 += u; n1++; }
        if (code & 4) { b2 += u; n2++; }
    }
    atomicAdd(&s_acc[0], a0);
    atomicAdd(&s_acc[1], b0);
    atomicAdd(&s_acc[2], b1);
    atomicAdd(&s_acc[3], b2);
    if (c == 0) {
        atomicAdd(&s_n[0], n0); atomicAdd(&s_n[1], n1); atomicAdd(&s_n[2], n2);
    }
    __syncthreads();
    if (threadIdx.x == 0) g_U0[c] = s_acc[0];
    if (threadIdx.x < 3) {
        g_Bk[threadIdx.x * CO + c] = s_acc[1 + threadIdx.x];
        if (c == 0) g_nbk[threadIdx.x] = (float)s_n[threadIdx.x];
    }
}

// ---------------- 5b) build V^T planes ----------------
__global__ void k_V() {
    int idx = blockIdx.x * 256 + threadIdx.x;
    if (idx >= NV * HW) return;
    int col = idx >> 12, q = idx & 4095;
    float v = 0.f;
    int code = g_codeB[q];
    if (col < 192) {
        int k = col >> 6, c = col & 63;
        v = ((code >> k) & 1) ? g_ufb[q * CO + c] : 0.f;
    } else if (col < 195) {
        v = (float)((code >> (col - 192)) & 1);
    }
    __nv_bfloat16 h = __float2bfloat16(v);
    g_Vthi[idx] = h;
    g_Vtlo[idx] = __float2bfloat16(v - __bfloat162float(h));
}

// ---------------- 6) GEMM1: split-bf16, 128x128, 2-stage k32 ----------------
#define G1_PLANE 10240              // 128 rows * 80 bytes
#define G1_SMEM  (2 * 4 * G1_PLANE) // 81920

__device__ __forceinline__ void g1_prefetch(uint32_t sb, int buf, int kc,
                                            int pb, int qb, int t) {
    int kof = kc * 32;
#pragma unroll
    for (int i = 0; i < 8; i++) {
        int v = t + i * 256;
        int plane = v >> 9, r = (v >> 2) & 127, seg = v & 3;
        uint32_t sa = sb + (uint32_t)(buf * (4 * G1_PLANE) + plane * G1_PLANE + r * 80 + seg * 16);
        const __nv_bfloat16* src = (plane == 0) ? g_faHi : (plane == 1) ? g_faLo
                                 : (plane == 2) ? g_fbHi : g_fbLo;
        int rowb = (plane < 2) ? pb : qb;
        cp16(sa, (const char*)src + ((size_t)(rowb + r) * CF + kof + seg * 8) * 2);
    }
}

__global__ void __launch_bounds__(256, 2) k_gemm_mma(int ybase) {
    extern __shared__ char smem[];
    uint32_t sb = smem_u32(smem);
    int t = threadIdx.x, w = t >> 5, l = t & 31;
    int qb = blockIdx.x << 7, pb = (ybase + blockIdx.y) << 7;
    int wm = w >> 1, wn = w & 1;

    float acc[2][8][4] = {};

    int rowA = wm * 32 + (l & 15);
    int rowB = wn * 64 + (l & 15);
    uint32_t colb = (uint32_t)((l >> 4) << 4);

    g1_prefetch(sb, 0, 0, pb, qb, t); CP_COMMIT;

    for (int kc = 0; kc < 8; kc++) {
        if (kc < 7) { g1_prefetch(sb, (kc + 1) & 1, kc + 1, pb, qb, t); CP_COMMIT; CP_WAIT1; }
        else CP_WAIT0;
        __syncthreads();

        uint32_t baseA = sb + (uint32_t)((kc & 1) * (4 * G1_PLANE));
        uint32_t baseB = baseA + 2 * G1_PLANE;

#pragma unroll
        for (int kk2 = 0; kk2 < 2; kk2++) {
            uint32_t kb = (uint32_t)(kk2 * 32) + colb;
            uint32_t ah[2][4], al[2][4];
#pragma unroll
            for (int mi = 0; mi < 2; mi++) {
                uint32_t ad = baseA + (uint32_t)((rowA + mi * 16) * 80) + kb;
                LDSM_X4(ah[mi][0], ah[mi][1], ah[mi][2], ah[mi][3], ad);
                LDSM_X4(al[mi][0], al[mi][1], al[mi][2], al[mi][3], ad + G1_PLANE);
            }
#pragma unroll
            for (int np = 0; np < 4; np++) {
                uint32_t bd = baseB + (uint32_t)((rowB + np * 16) * 80) + kb;
                uint32_t bh[4], bl[4];
                LDSM_X4(bh[0], bh[1], bh[2], bh[3], bd);
                LDSM_X4(bl[0], bl[1], bl[2], bl[3], bd + G1_PLANE);
                mma_bf16(acc[0][np * 2 + 0], ah[0], bh[0], bh[2]);
                mma_bf16(acc[0][np * 2 + 1], ah[0], bh[1], bh[3]);
                mma_bf16(acc[1][np * 2 + 0], ah[1], bh[0], bh[2]);
                mma_bf16(acc[1][np * 2 + 1], ah[1], bh[1], bh[3]);
                mma_bf16(acc[0][np * 2 + 0], ah[0], bl[0], bl[2]);
                mma_bf16(acc[0][np * 2 + 1], ah[0], bl[1], bl[3]);
                mma_bf16(acc[1][np * 2 + 0], ah[1], bl[0], bl[2]);
                mma_bf16(acc[1][np * 2 + 1], ah[1], bl[1], bl[3]);
                mma_bf16(acc[0][np * 2 + 0], al[0], bh[0], bh[2]);
                mma_bf16(acc[0][np * 2 + 1], al[0], bh[1], bh[3]);
                mma_bf16(acc[1][np * 2 + 0], al[1], bh[0], bh[2]);
                mma_bf16(acc[1][np * 2 + 1], al[1], bh[1], bh[3]);
            }
        }
        __syncthreads();
    }

    // ---- epilogue: exp + bf16 hi/lo plane stores ----
    int prl = wm * 32 + (l >> 2);
    int qcl = wn * 64 + (l & 3) * 2;
#pragma unroll
    for (int mi = 0; mi < 2; mi++) {
#pragma unroll
        for (int nj = 0; nj < 8; nj++) {
#pragma unroll
            for (int half = 0; half < 2; half++) {
                int rloc = prl + mi * 16 + half * 8;
                int qloc = qcl + nj * 8;
                float x0 = __expf(fminf(ALPHA * acc[mi][nj][half * 2 + 0], 80.f));
                float x1 = __expf(fminf(ALPHA * acc[mi][nj][half * 2 + 1], 80.f));
                __nv_bfloat16 h0 = __float2bfloat16(x0);
                __nv_bfloat16 h1 = __float2bfloat16(x1);
                __nv_bfloat16 lo0 = __float2bfloat16(x0 - __bfloat162float(h0));
                __nv_bfloat16 lo1 = __float2bfloat16(x1 - __bfloat162float(h1));
                __nv_bfloat162 hp; hp.x = h0; hp.y = h1;
                __nv_bfloat162 lp; lp.x = lo0; lp.y = lo1;
                size_t idx = ((size_t)(pb + rloc) * HW + qb + qloc) >> 1;
                g_Xhi[idx] = *(uint32_t*)&hp;
                g_Xlo[idx] = *(uint32_t*)&lp;
            }
        }
    }
}

// ---------------- 7) GEMM2: W = X @ V^T, 4-stage k16, 8-way k-split ----------------
#define G2_RS 48
#define G2_APLANE (64 * G2_RS)
#define G2_BPLANE (NV * G2_RS)
#define G2_STAGE (2 * G2_APLANE + 2 * G2_BPLANE)
#define G2_SMEM  (4 * G2_STAGE)
#define G2_SLOTS (256 + 2 * NV * 2)

__device__ __forceinline__ void g2_prefetch(uint32_t sb, int s, int qof, int pb, int t) {
#pragma unroll
    for (int i = 0; i < 5; i++) {
        int v = t + i * 256;
        if (v >= G2_SLOTS) break;
        if (v < 256) {
            int plane = v >> 7, r = (v >> 1) & 63, seg = v & 1;
            uint32_t sa = sb + (uint32_t)(s * G2_STAGE + plane * G2_APLANE + r * G2_RS + seg * 16);
            const uint32_t* xp = plane ? g_Xlo : g_Xhi;
            cp16(sa, (const char*)xp + ((size_t)(pb + r) * HW + qof) * 2 + seg * 16);
        } else {
            int v2 = v - 256;
            int plane = (v2 >= NV * 2) ? 1 : 0;
            int r = (v2 - plane * NV * 2) >> 1, seg = v2 & 1;
            uint32_t sa = sb + (uint32_t)(s * G2_STAGE + 2 * G2_APLANE + plane * G2_BPLANE + r * G2_RS + seg * 16);
            const __nv_bfloat16* vp = plane ? g_Vtlo : g_Vthi;
            cp16(sa, (const char*)vp + ((size_t)r * HW + qof + seg * 8) * 2);
        }
    }
}

__global__ void __launch_bounds__(256, 2) k_gemm2(int pbase) {
    extern __shared__ char smem[];
    uint32_t sb = smem_u32(smem);
    int t = threadIdx.x, w = t >> 5, l = t & 31;
    int pb = (pbase + blockIdx.x) << 6;
    int q0 = blockIdx.y << 9;           // 512-q range per k-split
    int wm = w & 3, wn = w >> 2;
    int nt = wn ? 6 : 7;

    float acc[14][4] = {};

    uint32_t arow = (uint32_t)((wm * 16 + (l & 15)) * G2_RS);
    uint32_t colb = (uint32_t)((l >> 4) << 4);

    g2_prefetch(sb, 0, q0, pb, t); CP_COMMIT;
    g2_prefetch(sb, 1, q0 + 16, pb, t); CP_COMMIT;
    g2_prefetch(sb, 2, q0 + 32, pb, t); CP_COMMIT;

    for (int kc = 0; kc < 32; kc++) {
        CP_WAIT2;
        __syncthreads();
        if (kc <= 28) g2_prefetch(sb, (kc + 3) & 3, q0 + (kc + 3) * 16, pb, t);
        CP_COMMIT;

        uint32_t baseA = sb + (uint32_t)((kc & 3) * G2_STAGE);
        uint32_t baseB = baseA + 2 * G2_APLANE;

        uint32_t ah[4], al[4];
        uint32_t ad = baseA + arow + colb;
        LDSM_X4(ah[0], ah[1], ah[2], ah[3], ad);
        LDSM_X4(al[0], al[1], al[2], al[3], ad + G2_APLANE);

        uint32_t bh[2][4], bl[2][4];
        {
            uint32_t bd = baseB + (uint32_t)((wn * 112 + (l & 15)) * G2_RS) + colb;
            LDSM_X4(bh[0][0], bh[0][1], bh[0][2], bh[0][3], bd);
            LDSM_X4(bl[0][0], bl[0][1], bl[0][2], bl[0][3], bd + G2_BPLANE);
        }
#pragma unroll
        for (int np = 0; np < 7; np++) {
            if (np < nt) {
                int cur = np & 1, nxt = cur ^ 1;
                if (np + 1 < nt) {
                    uint32_t bd = baseB + (uint32_t)((wn * 112 + (np + 1) * 16 + (l & 15)) * G2_RS) + colb;
                    LDSM_X4(bh[nxt][0], bh[nxt][1], bh[nxt][2], bh[nxt][3], bd);
                    LDSM_X4(bl[nxt][0], bl[nxt][1], bl[nxt][2], bl[nxt][3], bd + G2_BPLANE);
                }
                mma_bf16(acc[np * 2 + 0], ah, bh[cur][0], bh[cur][2]);
                mma_bf16(acc[np * 2 + 1], ah, bh[cur][1], bh[cur][3]);
                mma_bf16(acc[np * 2 + 0], ah, bl[cur][0], bl[cur][2]);
                mma_bf16(acc[np * 2 + 1], ah, bl[cur][1], bl[cur][3]);
                mma_bf16(acc[np * 2 + 0], al, bh[cur][0], bh[cur][2]);
                mma_bf16(acc[np * 2 + 1], al, bh[cur][1], bh[cur][3]);
            }
        }
    }

    int r0 = pb + wm * 16 + (l >> 2);
    int cb2 = (l & 3) * 2;
    float* Wp = g_Wpart + (size_t)blockIdx.y * HW * NV;
#pragma unroll
    for (int np = 0; np < 7; np++) {
        if (np < nt) {
#pragma unroll
            for (int n8 = 0; n8 < 2; n8++) {
                int col = wn * 112 + np * 16 + n8 * 8 + cb2;
                float* a = acc[np * 2 + n8];
                *(float2*)&Wp[(size_t)r0 * NV + col]       = make_float2(a[0], a[1]);
                *(float2*)&Wp[(size_t)(r0 + 8) * NV + col] = make_float2(a[2], a[3]);
            }
        }
    }
}

// ---------------- 8) combine (reads k-split partials directly) ----------------
__global__ void k_combine() {
    int idx = blockIdx.x * 256 + threadIdx.x;
    if (idx >= HW * CO) return;
    int p = idx >> 6, c = idx & 63;
    float comb = 0.f, msum = 0.f;
#pragma unroll
    for (int k = 0; k < 3; k++) {
        if (g_maskA[k * HW + p]) {
            msum += 1.f;
            float E = 0.f, Wv = 0.f;
#pragma unroll
            for (int ks = 0; ks < KSPLIT; ks++) {
                const float* Wp = g_Wpart + (size_t)ks * HW * NV + (size_t)p * NV;
                E  += Wp[192 + k];
                Wv += Wp[k * 64 + c];
            }
            float denom = E + (4096.0f - g_nbk[k]);
            comb += (Wv + g_U0[c] - g_Bk[k * CO + c]) / denom;
        }
    }
    g_aligned[idx] = comb / fmaxf(msum, 1.0f);
}

// ---------------- 9) bilinear upsample 64 -> 256 ----------------
__global__ void __launch_bounds__(256) k_up(float* __restrict__ out) {
    __shared__ float sm[64 * 65];
    int t = threadIdx.x;
    int Y = blockIdx.x;
    const float sc = 63.0f / 255.0f;
    float ry = (float)Y * sc;
    int y0 = (int)ry;
    int y1 = min(y0 + 1, 63);
    float wy = ry - (float)y0;

    const float* A0 = g_aligned + (size_t)(y0 << 6) * CO;
    const float* A1 = g_aligned + (size_t)(y1 << 6) * CO;
#pragma unroll
    for (int i = 0; i < 16; i++) {
        int v = t + i * 256;
        int x = v >> 6, c = v & 63;
        float a = A0[v], b = A1[v];
        sm[c * 65 + x] = a + (b - a) * wy;
    }
    __syncthreads();

#pragma unroll
    for (int i = 0; i < 64; i++) {
        int v = t + i * 256;
        int c = v >> 8, X = v & 255;
        float rx = (float)X * sc;
        int x0 = (int)rx;
        int x1 = min(x0 + 1, 63);
        float wx = rx - (float)x0;
        float a = sm[c * 65 + x0], b = sm[c * 65 + x1];
        out[(size_t)c * 65536 + Y * 256 + X] = a + (b - a) * wx;
    }
}

// ---------------- launch ----------------
extern "C" void kernel_launch(void* const* d_in, const int* in_sizes, int n_in,
                              void* d_out, int out_size) {
    const float* ufb_in = (const float*)d_in[0];   // (1,64,256,256)
    const float* fa     = (const float*)d_in[1];   // (1,256,64,64)
    const int*   fap    = (const int*)  d_in[2];   // (1,4,256,256)
    const float* fb     = (const float*)d_in[3];   // (1,256,64,64)
    const int*   fbp    = (const int*)  d_in[4];   // (1,4,256,256)
    float* out = (float*)d_out;                    // (1,64,256,256)

    static cudaStream_t s1 = nullptr;
    static cudaEvent_t e0 = nullptr, eV = nullptr, eA = nullptr, e2a = nullptr;
    if (!s1) {
        cudaStreamCreateWithFlags(&s1, cudaStreamNonBlocking);
        cudaEventCreateWithFlags(&e0, cudaEventDisableTiming);
        cudaEventCreateWithFlags(&eV, cudaEventDisableTiming);
        cudaEventCreateWithFlags(&eA, cudaEventDisableTiming);
        cudaEventCreateWithFlags(&e2a, cudaEventDisableTiming);
        cudaFuncSetAttribute(k_gemm_mma, cudaFuncAttributeMaxDynamicSharedMemorySize, G1_SMEM);
        cudaFuncSetAttribute(k_gemm2,    cudaFuncAttributeMaxDynamicSharedMemorySize, G2_SMEM);
    }

    // fork: side stream handles the value/mask prep chain (independent of GEMM1)
    cudaEventRecord(e0, 0);
    cudaStreamWaitEvent(s1, e0, 0);

    k_mean<<<512, 256>>>(fa, fb);                          // s0
    k_norm<<<dim3(128, 2), 256>>>(fa, fb);                 // s0
    k_masks<<<16, 256, 0, s1>>>(fap, fbp);                 // s1
    k_gemm_mma<<<dim3(32, 16), 256, G1_SMEM>>>(0);         // s0: GEMM1a (p 0..2047), profiled
    k_ufb<<<(HW * CO) / 256, 256, 0, s1>>>(ufb_in);        // s1, overlaps GEMM1a
    k_ub<<<64, 256, 0, s1>>>();                            // s1
    k_V<<<(NV * HW) / 256, 256, 0, s1>>>();                // s1
    cudaEventRecord(eV, s1);

    cudaEventRecord(eA, 0);                                // GEMM1a done
    k_gemm_mma<<<dim3(32, 16), 256, G1_SMEM>>>(16);        // s0: GEMM1b (p 2048..4095)

    // s1: GEMM2a on p-half 0, co-runs with GEMM1b
    cudaStreamWaitEvent(s1, eA, 0);
    k_gemm2<<<dim3(32, KSPLIT), 256, G2_SMEM, s1>>>(0);
    cudaEventRecord(e2a, s1);

    // s0: GEMM2b on p-half 1 (after GEMM1b in-order; needs V)
    cudaStreamWaitEvent(0, eV, 0);
    k_gemm2<<<dim3(32, KSPLIT), 256, G2_SMEM>>>(32);

    cudaStreamWaitEvent(0, e2a, 0);                        // join GEMM2a
    k_combine<<<(HW * CO) / 256, 256>>>();
    k_up<<<256, 256>>>(out);
}

// round 13
// speedup vs baseline: 1.3761x; 1.0947x over previous
#include <cuda_runtime.h>
#include <cuda_bf16.h>
#include <math.h>
#include <stdint.h>

#define HW 4096         // 64*64 spatial positions at feature res
#define CF 256          // feature channels
#define CO 64           // value channels (unalign_fb)
#define ALPHA 100.0f
#define XQ 4224         // padded (sorted) q length: 4096 + 8*16
#define XCH 264         // XQ/16 chunks
#define NV2 80          // GEMM2 cols: 64 ufb + 1 ones + 15 pad (5 n16 tiles)

// ---------------- device scratch (allocation-free) ----------------
__device__ uint32_t g_Xhi[(size_t)HW * XQ / 2]; // bf16x2 hi plane (permuted q order)
__device__ uint32_t g_Xlo[(size_t)HW * XQ / 2]; // bf16x2 lo plane
__device__ __nv_bfloat16 g_faHi[HW * CF];
__device__ __nv_bfloat16 g_faLo[HW * CF];
__device__ __nv_bfloat16 g_fbHi[HW * CF];
__device__ __nv_bfloat16 g_fbLo[HW * CF];
__device__ __nv_bfloat16 g_Vthi[NV2 * XQ];   // V^T [col][pos]
__device__ __nv_bfloat16 g_Vtlo[NV2 * XQ];
__device__ float g_Wpart[32 * HW * NV2];     // (plane*4+slot) partials
__device__ float g_ufb[HW * CO];             // downsampled values, [q][c]
__device__ float g_meanA[CF];
__device__ float g_meanB[CF];
__device__ unsigned char g_maskA[3 * HW];
__device__ unsigned char g_codeB[HW];        // 3-bit code of mask_b per q
__device__ int g_perm[XQ];                   // pos -> original q (-1 = dummy)
__device__ unsigned char g_chunkSeg[XCH];    // seg(code) per 16-q chunk
__device__ unsigned char g_slotSeg[32];      // seg per Wpart slot (0 = unused/ignored)
__device__ float g_U0[CO];                   // sum_q ufb[q][c]
__device__ float g_Bk[3 * CO];               // B_k[c] = sum_{q in mb_k} ufb[q][c]
__device__ float g_nbk[3];                   // |mb_k|
__device__ float g_aligned[HW * CO];         // [p][c]

// ---------------- helpers ----------------
__device__ __forceinline__ uint32_t smem_u32(const void* p) {
    uint32_t a;
    asm("{ .reg .u64 t; cvta.to.shared.u64 t, %1; cvt.u32.u64 %0, t; }" : "=r"(a) : "l"(p));
    return a;
}

#define LDSM_X4(r0, r1, r2, r3, addr) \
    asm volatile("ldmatrix.sync.aligned.m8n8.x4.shared.b16 {%0,%1,%2,%3}, [%4];" \
        : "=r"(r0), "=r"(r1), "=r"(r2), "=r"(r3) : "r"(addr))

__device__ __forceinline__ void mma_bf16(float* c, const uint32_t* a, uint32_t b0, uint32_t b1) {
    asm volatile(
        "mma.sync.aligned.m16n8k16.row.col.f32.bf16.bf16.f32 "
        "{%0,%1,%2,%3}, {%4,%5,%6,%7}, {%8,%9}, {%0,%1,%2,%3};"
        : "+f"(c[0]), "+f"(c[1]), "+f"(c[2]), "+f"(c[3])
        : "r"(a[0]), "r"(a[1]), "r"(a[2]), "r"(a[3]), "r"(b0), "r"(b1));
}

__device__ __forceinline__ void cp16(uint32_t saddr, const void* g) {
    asm volatile("cp.async.cg.shared.global [%0], [%1], 16;" :: "r"(saddr), "l"(g));
}
#define CP_COMMIT asm volatile("cp.async.commit_group;" ::: "memory")
#define CP_WAIT0  asm volatile("cp.async.wait_group 0;" ::: "memory")
#define CP_WAIT1  asm volatile("cp.async.wait_group 1;" ::: "memory")
#define CP_WAIT2  asm volatile("cp.async.wait_group 2;" ::: "memory")

// ---------------- 1) masks + deterministic stable code-sort (one block) ----------------
__global__ void __launch_bounds__(512) k_maskperm(const int* __restrict__ fap,
                                                  const int* __restrict__ fbp) {
    __shared__ int s_cnt[8][513];
    __shared__ int s_start[9];
    int t = threadIdx.x;
    for (int i = t; i < XQ; i += 512) g_perm[i] = -1;
    if (t < 32) g_slotSeg[t] = 0;

    int codes[8];
#pragma unroll
    for (int j = 0; j < 8; j++) {
        int q = t * 8 + j;
        int y = (q >> 6) << 2, x = (q & 63) << 2;
        int off = y * 256 + x;
        unsigned code = 0;
#pragma unroll
        for (int k = 0; k < 3; k++) {
            g_maskA[k * HW + q] = (fap[(k + 1) * 65536 + off] != 0) ? 1 : 0;
            if (fbp[(k + 1) * 65536 + off] != 0) code |= (1u << k);
        }
        g_codeB[q] = (unsigned char)code;
        codes[j] = (int)code;
    }
    int c8[8] = {0, 0, 0, 0, 0, 0, 0, 0};
#pragma unroll
    for (int j = 0; j < 8; j++) c8[codes[j]]++;
#pragma unroll
    for (int c = 0; c < 8; c++) s_cnt[c][t + 1] = c8[c];
    if (t == 0)
#pragma unroll
        for (int c = 0; c < 8; c++) s_cnt[c][0] = 0;
    __syncthreads();
    for (int s = 1; s < 512; s <<= 1) {
        int v[8];
#pragma unroll
        for (int c = 0; c < 8; c++) v[c] = (t + 1 > s) ? s_cnt[c][t + 1 - s] : 0;
        __syncthreads();
#pragma unroll
        for (int c = 0; c < 8; c++) s_cnt[c][t + 1] += v[c];
        __syncthreads();
    }
    if (t == 0) {
        int st = 0;
        for (int c = 0; c < 8; c++) { s_start[c] = st; st += (s_cnt[c][512] + 15) & ~15; }
        s_start[8] = st;
    }
    __syncthreads();
    int run[8];
#pragma unroll
    for (int c = 0; c < 8; c++) run[c] = s_start[c] + s_cnt[c][t];
#pragma unroll
    for (int j = 0; j < 8; j++) {
        int c = codes[j];
        g_perm[run[c]] = t * 8 + j;
        run[c]++;
    }
    if (t < XCH) {
        int pos = t * 16, sg = 0;
        for (int c = 0; c < 8; c++)
            if (pos >= s_start[c] && pos < s_start[c + 1]) sg = c;
        if (pos >= s_start[8]) sg = 0;
        g_chunkSeg[t] = (unsigned char)sg;
    }
}

// ---------------- 2) per-channel spatial means ----------------
__global__ void k_mean(const float* __restrict__ fa, const float* __restrict__ fb) {
    int cb = blockIdx.x;
    int ch = cb & 255;
    const float* src = (cb < 256) ? fa : fb;
    float s = 0.f;
    for (int i = threadIdx.x; i < HW; i += 256) s += src[ch * HW + i];
    __shared__ float red[256];
    red[threadIdx.x] = s;
    __syncthreads();
    for (int st = 128; st > 0; st >>= 1) {
        if (threadIdx.x < st) red[threadIdx.x] += red[threadIdx.x + st];
        __syncthreads();
    }
    if (threadIdx.x == 0) {
        float m = red[0] / (float)HW;
        if (cb < 256) g_meanA[ch] = m; else g_meanB[ch] = m;
    }
}

// ---------------- 3) center + normalize + split, smem-transposed ----------------
__global__ void __launch_bounds__(256) k_norm(const float* __restrict__ fa,
                                              const float* __restrict__ fb) {
    __shared__ float sm[256 * 33];
    int t = threadIdx.x;
    int pb = blockIdx.x * 32;
    const float* src;  const float* mean;
    __nv_bfloat16 *dHi, *dLo;
    if (blockIdx.y == 0) { src = fa; mean = g_meanA; dHi = g_faHi; dLo = g_faLo; }
    else                 { src = fb; mean = g_meanB; dHi = g_fbHi; dLo = g_fbLo; }

#pragma unroll
    for (int i = 0; i < 32; i++) {
        int v = t + i * 256;
        int c = v >> 5, p = v & 31;
        sm[c * 33 + p] = src[c * HW + pb + p] - mean[c];
    }
    __syncthreads();

    int p = t >> 3, part = t & 7;
    float nsq = 0.f;
#pragma unroll
    for (int j = 0; j < 32; j++) {
        int c = part * 32 + ((j + part * 4) & 31);
        float v = sm[c * 33 + p];
        nsq += v * v;
    }
    nsq += __shfl_xor_sync(0xFFFFFFFF, nsq, 1);
    nsq += __shfl_xor_sync(0xFFFFFFFF, nsq, 2);
    nsq += __shfl_xor_sync(0xFFFFFFFF, nsq, 4);
    float inv = rsqrtf(nsq);

    size_t base = ((size_t)(pb + p) * CF + part * 32);
    uint32_t* hdst = (uint32_t*)(dHi + base);
    uint32_t* ldst = (uint32_t*)(dLo + base);
#pragma unroll
    for (int j = 0; j < 16; j++) {
        int c = part * 32 + j * 2;
        float v0 = sm[(c + 0) * 33 + p] * inv;
        float v1 = sm[(c + 1) * 33 + p] * inv;
        __nv_bfloat16 h0 = __float2bfloat16(v0), h1 = __float2bfloat16(v1);
        __nv_bfloat162 hp; hp.x = h0; hp.y = h1;
        __nv_bfloat16 l0 = __float2bfloat16(v0 - __bfloat162float(h0));
        __nv_bfloat16 l1 = __float2bfloat16(v1 - __bfloat162float(h1));
        __nv_bfloat162 lp; lp.x = l0; lp.y = l1;
        hdst[j] = *(uint32_t*)&hp;
        ldst[j] = *(uint32_t*)&lp;
    }
}

// ---------------- 4) bilinear downsample 256->64 ----------------
__global__ void k_ufb(const float* __restrict__ ub) {
    int idx = blockIdx.x * 256 + threadIdx.x;
    if (idx >= HW * CO) return;
    int c = idx & 63, q = idx >> 6;
    int i = q >> 6, j = q & 63;
    const float sc = 255.0f / 63.0f;
    float ry = (float)i * sc, rx = (float)j * sc;
    int y0 = (int)ry, x0 = (int)rx;
    int y1 = min(y0 + 1, 255), x1 = min(x0 + 1, 255);
    float wy = ry - (float)y0, wx = rx - (float)x0;
    const float* b = ub + c * 65536;
    float v00 = b[y0 * 256 + x0], v01 = b[y0 * 256 + x1];
    float v10 = b[y1 * 256 + x0], v11 = b[y1 * 256 + x1];
    float r0 = v00 * (1.f - wy) + v10 * wy;
    float r1 = v01 * (1.f - wy) + v11 * wy;
    g_ufb[q * CO + c] = r0 * (1.f - wx) + r1 * wx;
}

// ---------------- 5) U0[c], Bk[k][c], nbk ----------------
__global__ void k_ub() {
    int c = blockIdx.x;
    __shared__ float s_acc[4];
    __shared__ int   s_n[3];
    if (threadIdx.x < 4) s_acc[threadIdx.x] = 0.f;
    if (threadIdx.x < 3) s_n[threadIdx.x] = 0;
    __syncthreads();
    float a0 = 0, b0 = 0, b1 = 0, b2 = 0;
    int n0 = 0, n1 = 0, n2 = 0;
    for (int q = threadIdx.x; q < HW; q += 256) {
        float u = g_ufb[q * CO + c];
        int code = g_codeB[q];
        a0 += u;
        if (code & 1) { b0 += u; n0++; }
        if (code & 2) { b1 += u; n1++; }
        if (code & 4) { b2 += u; n2++; }
    }
    atomicAdd(&s_acc[0], a0);
    atomicAdd(&s_acc[1], b0);
    atomicAdd(&s_acc[2], b1);
    atomicAdd(&s_acc[3], b2);
    if (c == 0) {
        atomicAdd(&s_n[0], n0); atomicAdd(&s_n[1], n1); atomicAdd(&s_n[2], n2);
    }
    __syncthreads();
    if (threadIdx.x == 0) g_U0[c] = s_acc[0];
    if (threadIdx.x < 3) {
        g_Bk[threadIdx.x * CO + c] = s_acc[1 + threadIdx.x];
        if (c == 0) g_nbk[threadIdx.x] = (float)s_n[threadIdx.x];
    }
}

// ---------------- 5b) build V^T planes (permuted rows; no masks needed) ----------------
__global__ void k_V() {
    int idx = blockIdx.x * 256 + threadIdx.x;   // col*XQ + pos
    if (idx >= NV2 * XQ) return;
    int col = idx / XQ, pos = idx % XQ;
    int q = g_perm[pos];
    float v = 0.f;
    if (q >= 0) {
        if (col < 64) v = g_ufb[q * CO + col];
        else if (col == 64) v = 1.0f;
    }
    __nv_bfloat16 h = __float2bfloat16(v);
    g_Vthi[idx] = h;
    g_Vtlo[idx] = __float2bfloat16(v - __bfloat162float(h));
}

// ---------------- 6) GEMM1: split-bf16, 128x128, 2-stage k32, permuted B rows ----------------
#define G1_PLANE 10240              // 128 rows * 80 bytes
#define G1_SMEM  (2 * 4 * G1_PLANE) // 81920

__device__ __forceinline__ void g1_prefetch(uint32_t sb, int buf, int kc,
                                            int pb, int qb, int t) {
    int kof = kc * 32;
#pragma unroll
    for (int i = 0; i < 8; i++) {
        int v = t + i * 256;
        int plane = v >> 9, r = (v >> 2) & 127, seg = v & 3;
        uint32_t sa = sb + (uint32_t)(buf * (4 * G1_PLANE) + plane * G1_PLANE + r * 80 + seg * 16);
        const __nv_bfloat16* src = (plane == 0) ? g_faHi : (plane == 1) ? g_faLo
                                 : (plane == 2) ? g_fbHi : g_fbLo;
        int row;
        if (plane < 2) row = pb + r;
        else { row = __ldg(&g_perm[qb + r]); if (row < 0) row = 0; }
        cp16(sa, (const char*)src + ((size_t)row * CF + kof + seg * 8) * 2);
    }
}

__global__ void __launch_bounds__(256, 2) k_gemm_mma() {
    extern __shared__ char smem[];
    uint32_t sb = smem_u32(smem);
    int t = threadIdx.x, w = t >> 5, l = t & 31;
    int qb = blockIdx.x << 7, pb = blockIdx.y << 7;
    int wm = w >> 1, wn = w & 1;

    float acc[2][8][4] = {};

    int rowA = wm * 32 + (l & 15);
    int rowB = wn * 64 + (l & 15);
    uint32_t colb = (uint32_t)((l >> 4) << 4);

    g1_prefetch(sb, 0, 0, pb, qb, t); CP_COMMIT;

    for (int kc = 0; kc < 8; kc++) {
        if (kc < 7) { g1_prefetch(sb, (kc + 1) & 1, kc + 1, pb, qb, t); CP_COMMIT; CP_WAIT1; }
        else CP_WAIT0;
        __syncthreads();

        uint32_t baseA = sb + (uint32_t)((kc & 1) * (4 * G1_PLANE));
        uint32_t baseB = baseA + 2 * G1_PLANE;

#pragma unroll
        for (int kk2 = 0; kk2 < 2; kk2++) {
            uint32_t kb = (uint32_t)(kk2 * 32) + colb;
            uint32_t ah[2][4], al[2][4];
#pragma unroll
            for (int mi = 0; mi < 2; mi++) {
                uint32_t ad = baseA + (uint32_t)((rowA + mi * 16) * 80) + kb;
                LDSM_X4(ah[mi][0], ah[mi][1], ah[mi][2], ah[mi][3], ad);
                LDSM_X4(al[mi][0], al[mi][1], al[mi][2], al[mi][3], ad + G1_PLANE);
            }
#pragma unroll
            for (int np = 0; np < 4; np++) {
                uint32_t bd = baseB + (uint32_t)((rowB + np * 16) * 80) + kb;
                uint32_t bh[4], bl[4];
                LDSM_X4(bh[0], bh[1], bh[2], bh[3], bd);
                LDSM_X4(bl[0], bl[1], bl[2], bl[3], bd + G1_PLANE);
                mma_bf16(acc[0][np * 2 + 0], ah[0], bh[0], bh[2]);
                mma_bf16(acc[0][np * 2 + 1], ah[0], bh[1], bh[3]);
                mma_bf16(acc[1][np * 2 + 0], ah[1], bh[0], bh[2]);
                mma_bf16(acc[1][np * 2 + 1], ah[1], bh[1], bh[3]);
                mma_bf16(acc[0][np * 2 + 0], ah[0], bl[0], bl[2]);
                mma_bf16(acc[0][np * 2 + 1], ah[0], bl[1], bl[3]);
                mma_bf16(acc[1][np * 2 + 0], ah[1], bl[0], bl[2]);
                mma_bf16(acc[1][np * 2 + 1], ah[1], bl[1], bl[3]);
                mma_bf16(acc[0][np * 2 + 0], al[0], bh[0], bh[2]);
                mma_bf16(acc[0][np * 2 + 1], al[0], bh[1], bh[3]);
                mma_bf16(acc[1][np * 2 + 0], al[1], bh[0], bh[2]);
                mma_bf16(acc[1][np * 2 + 1], al[1], bh[1], bh[3]);
            }
        }
        __syncthreads();
    }

    // ---- epilogue: exp + bf16 hi/lo plane stores (permuted-q columns) ----
    int prl = wm * 32 + (l >> 2);
    int qcl = wn * 64 + (l & 3) * 2;
#pragma unroll
    for (int mi = 0; mi < 2; mi++) {
#pragma unroll
        for (int nj = 0; nj < 8; nj++) {
#pragma unroll
            for (int half = 0; half < 2; half++) {
                int rloc = prl + mi * 16 + half * 8;
                int qloc = qcl + nj * 8;
                float x0 = __expf(fminf(ALPHA * acc[mi][nj][half * 2 + 0], 80.f));
                float x1 = __expf(fminf(ALPHA * acc[mi][nj][half * 2 + 1], 80.f));
                __nv_bfloat16 h0 = __float2bfloat16(x0);
                __nv_bfloat16 h1 = __float2bfloat16(x1);
                __nv_bfloat16 lo0 = __float2bfloat16(x0 - __bfloat162float(h0));
                __nv_bfloat16 lo1 = __float2bfloat16(x1 - __bfloat162float(h1));
                __nv_bfloat162 hp; hp.x = h0; hp.y = h1;
                __nv_bfloat162 lp; lp.x = lo0; lp.y = lo1;
                size_t idx = ((size_t)(pb + rloc) * XQ + qb + qloc) >> 1;
                g_Xhi[idx] = *(uint32_t*)&hp;
                g_Xlo[idx] = *(uint32_t*)&lp;
            }
        }
    }
}

// ---------------- 7) GEMM2: per-segment W = X @ V^T (80 cols), 4-stage k16 ----------------
#define W2RS 48
#define W2A (64 * W2RS)                 // 3072
#define W2B (NV2 * W2RS)                // 3840
#define W2ST (2 * W2A + 2 * W2B)        // 13824
#define W2SMEM (4 * W2ST)               // 55296
#define W2SLOTS (256 + 320)             // A: 64*2*2, B: 80*2*2

__device__ __forceinline__ void g2_prefetch(uint32_t sb, int s, int qof, int pb, int t) {
#pragma unroll
    for (int i = 0; i < 3; i++) {
        int v = t + i * 256;
        if (v >= W2SLOTS) break;
        if (v < 256) {
            int plane = v >> 7, r = (v >> 1) & 63, seg = v & 1;
            uint32_t sa = sb + (uint32_t)(s * W2ST + plane * W2A + r * W2RS + seg * 16);
            const uint32_t* xp = plane ? g_Xlo : g_Xhi;
            cp16(sa, (const char*)xp + ((size_t)(pb + r) * XQ + qof) * 2 + seg * 16);
        } else {
            int v2 = v - 256;
            int plane = (v2 >= NV2 * 2) ? 1 : 0;
            int r = (v2 - plane * NV2 * 2) >> 1, seg = v2 & 1;
            uint32_t sa = sb + (uint32_t)(s * W2ST + 2 * W2A + plane * W2B + r * W2RS + seg * 16);
            const __nv_bfloat16* vp = plane ? g_Vtlo : g_Vthi;
            cp16(sa, (const char*)vp + ((size_t)r * XQ + qof + seg * 8) * 2);
        }
    }
}

__device__ __forceinline__ void g2_flush(float acc[6][4], int nt, int pb, int wm, int wn,
                                         int l, int plane, int slot, int seg) {
    float* Wp = g_Wpart + (size_t)(plane * 4 + slot) * HW * NV2;
    int r0 = pb + wm * 16 + (l >> 2);
    int cb2 = (l & 3) * 2;
#pragma unroll
    for (int np = 0; np < 3; np++) {
        if (np < nt) {
#pragma unroll
            for (int n8 = 0; n8 < 2; n8++) {
                int col = wn * 48 + np * 16 + n8 * 8 + cb2;
                float* a = acc[np * 2 + n8];
                *(float2*)&Wp[(size_t)r0 * NV2 + col]       = make_float2(a[0], a[1]);
                *(float2*)&Wp[(size_t)(r0 + 8) * NV2 + col] = make_float2(a[2], a[3]);
                a[0] = a[1] = a[2] = a[3] = 0.f;
            }
        }
    }
    if (threadIdx.x == 0) g_slotSeg[plane * 4 + slot] = (unsigned char)seg;
}

__global__ void __launch_bounds__(256, 2) k_gemm2() {
    extern __shared__ char smem[];
    uint32_t sb = smem_u32(smem);
    int t = threadIdx.x, w = t >> 5, l = t & 31;
    int pb = blockIdx.x << 6;
    int plane = blockIdx.y;           // 0..7
    int cbase = plane * 33;
    int q0 = plane * 528;
    int wm = w & 3, wn = w >> 2;
    int nt = wn ? 2 : 3;

    float acc[6][4] = {};
    int curSeg = g_chunkSeg[cbase];
    int slot = 0;

    uint32_t arow = (uint32_t)((wm * 16 + (l & 15)) * W2RS);
    uint32_t colb = (uint32_t)((l >> 4) << 4);

    g2_prefetch(sb, 0, q0, pb, t); CP_COMMIT;
    g2_prefetch(sb, 1, q0 + 16, pb, t); CP_COMMIT;
    g2_prefetch(sb, 2, q0 + 32, pb, t); CP_COMMIT;

    for (int kc = 0; kc < 33; kc++) {
        CP_WAIT2;
        __syncthreads();
        if (kc <= 29) g2_prefetch(sb, (kc + 3) & 3, q0 + (kc + 3) * 16, pb, t);
        CP_COMMIT;

        int sg = g_chunkSeg[cbase + kc];
        if (sg != curSeg) {
            g2_flush(acc, nt, pb, wm, wn, l, plane, slot, curSeg);
            slot = min(slot + 1, 3);
            curSeg = sg;
        }

        uint32_t baseA = sb + (uint32_t)((kc & 3) * W2ST);
        uint32_t baseB = baseA + 2 * W2A;

        uint32_t ah[4], al[4];
        uint32_t ad = baseA + arow + colb;
        LDSM_X4(ah[0], ah[1], ah[2], ah[3], ad);
        LDSM_X4(al[0], al[1], al[2], al[3], ad + W2A);
#pragma unroll
        for (int np = 0; np < 3; np++) {
            if (np < nt) {
                uint32_t bd = baseB + (uint32_t)((wn * 48 + np * 16 + (l & 15)) * W2RS) + colb;
                uint32_t bh[4], bl[4];
                LDSM_X4(bh[0], bh[1], bh[2], bh[3], bd);
                LDSM_X4(bl[0], bl[1], bl[2], bl[3], bd + W2B);
                mma_bf16(acc[np * 2 + 0], ah, bh[0], bh[2]);
                mma_bf16(acc[np * 2 + 1], ah, bh[1], bh[3]);
                mma_bf16(acc[np * 2 + 0], ah, bl[0], bl[2]);
                mma_bf16(acc[np * 2 + 1], ah, bl[1], bl[3]);
                mma_bf16(acc[np * 2 + 0], al, bh[0], bh[2]);
                mma_bf16(acc[np * 2 + 1], al, bh[1], bh[3]);
            }
        }
    }
    g2_flush(acc, nt, pb, wm, wn, l, plane, slot, curSeg);
}

// ---------------- 8) combine: sum slots by code-bit membership ----------------
__global__ void k_combine() {
    int idx = blockIdx.x * 256 + threadIdx.x;   // p*64 + c
    if (idx >= HW * CO) return;
    int p = idx >> 6, c = idx & 63;
    float Wk[3] = {0.f, 0.f, 0.f}, Ek[3] = {0.f, 0.f, 0.f};
#pragma unroll
    for (int s = 0; s < 32; s++) {
        int sg = g_slotSeg[s];
        if (!sg) continue;
        const float* Wp = g_Wpart + (size_t)s * HW * NV2 + (size_t)p * NV2;
        float wv = Wp[c], ev = Wp[64];
        if (sg & 1) { Wk[0] += wv; Ek[0] += ev; }
        if (sg & 2) { Wk[1] += wv; Ek[1] += ev; }
        if (sg & 4) { Wk[2] += wv; Ek[2] += ev; }
    }
    float comb = 0.f, msum = 0.f;
#pragma unroll
    for (int k = 0; k < 3; k++) {
        if (g_maskA[k * HW + p]) {
            msum += 1.f;
            float denom = Ek[k] + (4096.0f - g_nbk[k]);
            comb += (Wk[k] + g_U0[c] - g_Bk[k * CO + c]) / denom;
        }
    }
    g_aligned[idx] = comb / fmaxf(msum, 1.0f);
}

// ---------------- 9) bilinear upsample 64 -> 256 ----------------
__global__ void __launch_bounds__(256) k_up(float* __restrict__ out) {
    __shared__ float sm[64 * 65];
    int t = threadIdx.x;
    int Y = blockIdx.x;
    const float sc = 63.0f / 255.0f;
    float ry = (float)Y * sc;
    int y0 = (int)ry;
    int y1 = min(y0 + 1, 63);
    float wy = ry - (float)y0;

    const float* A0 = g_aligned + (size_t)(y0 << 6) * CO;
    const float* A1 = g_aligned + (size_t)(y1 << 6) * CO;
#pragma unroll
    for (int i = 0; i < 16; i++) {
        int v = t + i * 256;
        int x = v >> 6, c = v & 63;
        float a = A0[v], b = A1[v];
        sm[c * 65 + x] = a + (b - a) * wy;
    }
    __syncthreads();

#pragma unroll
    for (int i = 0; i < 64; i++) {
        int v = t + i * 256;
        int c = v >> 8, X = v & 255;
        float rx = (float)X * sc;
        int x0 = (int)rx;
        int x1 = min(x0 + 1, 63);
        float wx = rx - (float)x0;
        float a = sm[c * 65 + x0], b = sm[c * 65 + x1];
        out[(size_t)c * 65536 + Y * 256 + X] = a + (b - a) * wx;
    }
}

// ---------------- launch ----------------
extern "C" void kernel_launch(void* const* d_in, const int* in_sizes, int n_in,
                              void* d_out, int out_size) {
    const float* ufb_in = (const float*)d_in[0];   // (1,64,256,256)
    const float* fa     = (const float*)d_in[1];   // (1,256,64,64)
    const int*   fap    = (const int*)  d_in[2];   // (1,4,256,256)
    const float* fb     = (const float*)d_in[3];   // (1,256,64,64)
    const int*   fbp    = (const int*)  d_in[4];   // (1,4,256,256)
    float* out = (float*)d_out;                    // (1,64,256,256)

    static cudaStream_t s1 = nullptr;
    static cudaEvent_t e0 = nullptr, ePerm = nullptr, eV = nullptr;
    if (!s1) {
        cudaStreamCreateWithFlags(&s1, cudaStreamNonBlocking);
        cudaEventCreateWithFlags(&e0, cudaEventDisableTiming);
        cudaEventCreateWithFlags(&ePerm, cudaEventDisableTiming);
        cudaEventCreateWithFlags(&eV, cudaEventDisableTiming);
        cudaFuncSetAttribute(k_gemm_mma, cudaFuncAttributeMaxDynamicSharedMemorySize, G1_SMEM);
        cudaFuncSetAttribute(k_gemm2,    cudaFuncAttributeMaxDynamicSharedMemorySize, W2SMEM);
    }

    // fork
    cudaEventRecord(e0, 0);
    cudaStreamWaitEvent(s1, e0, 0);

    k_maskperm<<<1, 512, 0, s1>>>(fap, fbp);               // 1 (s1): masks + sort
    cudaEventRecord(ePerm, s1);
    k_mean<<<512, 256>>>(fa, fb);                          // 2 (s0)
    k_norm<<<dim3(128, 2), 256>>>(fa, fb);                 // 3 (s0)
    cudaStreamWaitEvent(0, ePerm, 0);
    k_gemm_mma<<<dim3(33, 32), 256, G1_SMEM>>>();          // 4 (s0) -> profiled
    k_ufb<<<(HW * CO) / 256, 256, 0, s1>>>(ufb_in);        // 5 (s1, overlaps GEMM1)
    k_ub<<<64, 256, 0, s1>>>();                            // 6 (s1)
    k_V<<<(NV2 * XQ + 255) / 256, 256, 0, s1>>>();         // 7 (s1)
    cudaEventRecord(eV, s1);
    cudaStreamWaitEvent(0, eV, 0);

    k_gemm2<<<dim3(64, 8), 256, W2SMEM>>>();
    k_combine<<<(HW * CO) / 256, 256>>>();
    k_up<<<256, 256>>>(out);
}